// round 1
// baseline (speedup 1.0000x reference)
#include <cuda_runtime.h>
#include <cuda_bf16.h>
#include <math.h>

// Problem dims
#define B_  4
#define T_  1024
#define V_  32000
#define D_  384
#define H_  6
#define HS_ 64
#define L_  6
#define DFF_ 1536
#define BT_ (B_*T_)
#define EPS_ 1e-5f
#define SCALE_ 0.125f   // 1/sqrt(64)

// ---------------- static scratch (no allocations allowed) ----------------
__device__ float g_x[BT_*D_];
__device__ float g_h[BT_*D_];
__device__ float g_q[H_*BT_*HS_];
__device__ float g_k[H_*BT_*HS_];
__device__ float g_v[H_*BT_*HS_];
__device__ float g_s[(size_t)B_*H_*T_*T_];
__device__ float g_av[BT_*D_];
__device__ float g_ffn[BT_*DFF_];
__device__ float g_rowloss[BT_];
__device__ float g_logits[(size_t)BT_*V_];   // fallback if d_out too small for logits

// ---------------- embed: x = tok_table[ids] + pos_table ----------------
__global__ void embed_kernel(const int* __restrict__ tok,
                             const float* __restrict__ tt,
                             const float* __restrict__ pt,
                             float* __restrict__ x)
{
    int idx = blockIdx.x * blockDim.x + threadIdx.x;
    if (idx >= BT_*D_) return;
    int bt = idx / D_;
    int d  = idx - bt * D_;
    int t  = bt % T_;
    x[idx] = tt[(size_t)tok[bt] * D_ + d] + pt[t * D_ + d];
}

// ---------------- layernorm: block per row, 128 threads, D=384 ----------------
__global__ void ln_kernel(const float* __restrict__ x,
                          const float* __restrict__ g,
                          const float* __restrict__ b,
                          float* __restrict__ y)
{
    __shared__ float rs[128], rq[128];
    int row = blockIdx.x;
    int tid = threadIdx.x;
    const float* xr = x + (size_t)row * D_;
    float s = 0.f, q = 0.f;
    #pragma unroll
    for (int i = tid; i < D_; i += 128) { float v = xr[i]; s += v; q += v*v; }
    rs[tid] = s; rq[tid] = q;
    __syncthreads();
    for (int off = 64; off > 0; off >>= 1) {
        if (tid < off) { rs[tid] += rs[tid+off]; rq[tid] += rq[tid+off]; }
        __syncthreads();
    }
    float mean = rs[0] / D_;
    float var  = rq[0] / D_ - mean * mean;
    float inv  = rsqrtf(var + EPS_);
    float* yr = y + (size_t)row * D_;
    #pragma unroll
    for (int i = tid; i < D_; i += 128)
        yr[i] = (xr[i] - mean) * inv * g[i] + b[i];
}

// ---------------- generic batched tiled GEMM ----------------
// C[M,N] = op(A[M,K] * B) (+bias) (+C if accumulate) (relu optional)
// transB==0: B is [K,N] row-major;  transB==1: B is [N,K] row-major (NT)
// z-batching: for z = blockIdx.z, zq=z/zdiv, zr=z%zdiv,
//   operand offset = zq*s?d + zr*s?m
__global__ void gemm_kernel(const float* __restrict__ A,
                            const float* __restrict__ B,
                            float* __restrict__ C,
                            const float* __restrict__ bias,
                            int M, int N, int K, int lda, int ldb, int ldc,
                            int transB, int accumulate, int relu,
                            int zdiv,
                            long long sAd, long long sAm,
                            long long sBd, long long sBm,
                            long long sCd, long long sCm)
{
    __shared__ float As[16][65];
    __shared__ float Bs[16][68];

    int z  = blockIdx.z;
    int zq = z / zdiv;
    int zr = z - zq * zdiv;
    A += zq * sAd + (long long)zr * sAm;
    B += zq * sBd + (long long)zr * sBm;
    C += zq * sCd + (long long)zr * sCm;

    int tid = threadIdx.x;
    int tx = tid & 15, ty = tid >> 4;
    int row0 = blockIdx.y * 64;
    int col0 = blockIdx.x * 64;

    float acc[4][4] = {};

    int a_row = tid >> 2;          // 0..63
    int a_col = (tid & 3) * 4;     // 0,4,8,12
    int bn_r  = tid >> 4;          // 0..15 (NN)
    int bn_c  = (tid & 15) * 4;    // 0..60 (NN)
    int bt_n  = tid >> 2;          // 0..63 (NT)
    int bt_k  = (tid & 3) * 4;     // (NT)

    for (int k0 = 0; k0 < K; k0 += 16) {
        float4 a4 = *(const float4*)&A[(size_t)(row0 + a_row) * lda + k0 + a_col];
        As[a_col+0][a_row] = a4.x;
        As[a_col+1][a_row] = a4.y;
        As[a_col+2][a_row] = a4.z;
        As[a_col+3][a_row] = a4.w;
        if (!transB) {
            float4 b4 = *(const float4*)&B[(size_t)(k0 + bn_r) * ldb + col0 + bn_c];
            Bs[bn_r][bn_c+0] = b4.x;
            Bs[bn_r][bn_c+1] = b4.y;
            Bs[bn_r][bn_c+2] = b4.z;
            Bs[bn_r][bn_c+3] = b4.w;
        } else {
            float4 b4 = *(const float4*)&B[(size_t)(col0 + bt_n) * ldb + k0 + bt_k];
            Bs[bt_k+0][bt_n] = b4.x;
            Bs[bt_k+1][bt_n] = b4.y;
            Bs[bt_k+2][bt_n] = b4.z;
            Bs[bt_k+3][bt_n] = b4.w;
        }
        __syncthreads();
        #pragma unroll
        for (int kk = 0; kk < 16; kk++) {
            float a[4], b[4];
            #pragma unroll
            for (int i = 0; i < 4; i++) a[i] = As[kk][ty*4+i];
            #pragma unroll
            for (int j = 0; j < 4; j++) b[j] = Bs[kk][tx*4+j];
            #pragma unroll
            for (int i = 0; i < 4; i++)
                #pragma unroll
                for (int j = 0; j < 4; j++)
                    acc[i][j] = fmaf(a[i], b[j], acc[i][j]);
        }
        __syncthreads();
    }

    #pragma unroll
    for (int i = 0; i < 4; i++) {
        int r = row0 + ty*4 + i;
        #pragma unroll
        for (int j = 0; j < 4; j++) {
            int c = col0 + tx*4 + j;
            float v = acc[i][j];
            if (bias) v += bias[c];
            size_t idx = (size_t)r * ldc + c;
            if (accumulate) v += C[idx];
            if (relu) v = fmaxf(v, 0.f);
            C[idx] = v;
        }
    }
}

// ---------------- softmax over scores rows (with the reference's tril*scale quirk)
// grid = B*H*T blocks, 256 threads. Row layout: S[(bh*T + t)*T + s]
__global__ void softmax_kernel(float* __restrict__ S)
{
    __shared__ float red[256];
    size_t row = blockIdx.x;
    int t = (int)(row % T_);
    float* p = S + row * T_;
    int tid = threadIdx.x;

    float vals[4];
    float m = -1e30f;
    #pragma unroll
    for (int j = 0; j < 4; j++) {
        int s = tid + j * 256;
        float v = (s <= t) ? p[s] * SCALE_ : 0.0f;
        vals[j] = v;
        m = fmaxf(m, v);
    }
    red[tid] = m; __syncthreads();
    for (int off = 128; off > 0; off >>= 1) {
        if (tid < off) red[tid] = fmaxf(red[tid], red[tid+off]);
        __syncthreads();
    }
    m = red[0]; __syncthreads();

    float sum = 0.f;
    #pragma unroll
    for (int j = 0; j < 4; j++) { vals[j] = __expf(vals[j] - m); sum += vals[j]; }
    red[tid] = sum; __syncthreads();
    for (int off = 128; off > 0; off >>= 1) {
        if (tid < off) red[tid] += red[tid+off];
        __syncthreads();
    }
    float inv = 1.0f / red[0];
    #pragma unroll
    for (int j = 0; j < 4; j++) p[tid + j*256] = vals[j] * inv;
}

// ---------------- loss: per-row logsumexp - gold ----------------
__global__ void lossrow_kernel(const float* __restrict__ logits,
                               const int* __restrict__ tgt,
                               float* __restrict__ rowloss)
{
    __shared__ float red[256];
    int row = blockIdx.x;
    int tid = threadIdx.x;
    const float* p = logits + (size_t)row * V_;

    float m = -1e30f;
    for (int s = tid; s < V_; s += 256) m = fmaxf(m, p[s]);
    red[tid] = m; __syncthreads();
    for (int off = 128; off > 0; off >>= 1) {
        if (tid < off) red[tid] = fmaxf(red[tid], red[tid+off]);
        __syncthreads();
    }
    m = red[0]; __syncthreads();

    float sum = 0.f;
    for (int s = tid; s < V_; s += 256) sum += __expf(p[s] - m);
    red[tid] = sum; __syncthreads();
    for (int off = 128; off > 0; off >>= 1) {
        if (tid < off) red[tid] += red[tid+off];
        __syncthreads();
    }
    if (tid == 0) {
        float lse = m + logf(red[0]);
        rowloss[row] = lse - p[tgt[row]];
    }
}

__global__ void lossreduce_kernel(const float* __restrict__ rowloss,
                                  float* __restrict__ out)
{
    __shared__ float red[256];
    int tid = threadIdx.x;
    float s = 0.f;
    for (int i = tid; i < BT_; i += 256) s += rowloss[i];
    red[tid] = s; __syncthreads();
    for (int off = 128; off > 0; off >>= 1) {
        if (tid < off) red[tid] += red[tid+off];
        __syncthreads();
    }
    if (tid == 0) out[0] = red[0] / (float)BT_;
}

// ---------------- host side ----------------
static float* sym(const void* s)
{
    void* p = nullptr;
    cudaGetSymbolAddress(&p, s);
    return (float*)p;
}

static void gemm(const float* A, const float* B, float* C, const float* bias,
                 int M, int N, int K, int lda, int ldb, int ldc,
                 bool transB, bool acc, bool relu,
                 int Z = 1, int zdiv = 1,
                 long long sAd = 0, long long sAm = 0,
                 long long sBd = 0, long long sBm = 0,
                 long long sCd = 0, long long sCm = 0)
{
    dim3 grid(N / 64, M / 64, Z);
    gemm_kernel<<<grid, 256>>>(A, B, C, bias, M, N, K, lda, ldb, ldc,
                               transB ? 1 : 0, acc ? 1 : 0, relu ? 1 : 0,
                               zdiv, sAd, sAm, sBd, sBm, sCd, sCm);
}

extern "C" void kernel_launch(void* const* d_in, const int* in_sizes, int n_in,
                              void* d_out, int out_size)
{
    const int*   token_ids = (const int*)d_in[0];
    const int*   targets   = (const int*)d_in[1];
    const float* tok_table = (const float*)d_in[2];
    const float* pos_table = (const float*)d_in[3];
    const float* ln1_g = (const float*)d_in[4];
    const float* ln1_b = (const float*)d_in[5];
    const float* Wq = (const float*)d_in[6];
    const float* Wk = (const float*)d_in[7];
    const float* Wv = (const float*)d_in[8];
    const float* Wo = (const float*)d_in[9];
    const float* ln2_g = (const float*)d_in[10];
    const float* ln2_b = (const float*)d_in[11];
    const float* W1 = (const float*)d_in[12];
    const float* b1 = (const float*)d_in[13];
    const float* W2 = (const float*)d_in[14];
    const float* b2 = (const float*)d_in[15];
    const float* lnf_g = (const float*)d_in[16];
    const float* lnf_b = (const float*)d_in[17];
    const float* Wlm = (const float*)d_in[18];
    const float* blm = (const float*)d_in[19];

    float* x   = sym(g_x);
    float* h   = sym(g_h);
    float* q   = sym(g_q);
    float* k   = sym(g_k);
    float* v   = sym(g_v);
    float* s   = sym(g_s);
    float* av  = sym(g_av);
    float* ffn = sym(g_ffn);
    float* rl  = sym(g_rowloss);

    const long long NLOGITS = (long long)BT_ * V_;
    float* logits;
    float* out = (float*)d_out;
    bool out_has_logits = ((long long)out_size >= NLOGITS);
    logits = out_has_logits ? out : sym(g_logits);

    // ---- embed ----
    embed_kernel<<<(BT_*D_ + 255)/256, 256>>>(token_ids, tok_table, pos_table, x);

    for (int l = 0; l < L_; l++) {
        // ln1
        ln_kernel<<<BT_, 128>>>(x, ln1_g + l*D_, ln1_b + l*D_, h);

        // q,k,v : per-head GEMM batched over z=h  (C layout [H, BT, HS])
        long long wOff = (long long)l * H_ * D_ * HS_;
        gemm(h, Wq + wOff, q, nullptr, BT_, HS_, D_, D_, HS_, HS_,
             false, false, false, H_, 1,
             0, 0, (long long)D_*HS_, 0, (long long)BT_*HS_, 0);
        gemm(h, Wk + wOff, k, nullptr, BT_, HS_, D_, D_, HS_, HS_,
             false, false, false, H_, 1,
             0, 0, (long long)D_*HS_, 0, (long long)BT_*HS_, 0);
        gemm(h, Wv + wOff, v, nullptr, BT_, HS_, D_, D_, HS_, HS_,
             false, false, false, H_, 1,
             0, 0, (long long)D_*HS_, 0, (long long)BT_*HS_, 0);

        // scores = q @ k^T : z = b*H + h
        gemm(q, k, s, nullptr, T_, T_, HS_, HS_, HS_, T_,
             true, false, false, B_*H_, H_,
             (long long)T_*HS_, (long long)BT_*HS_,     // A: b -> T*HS, h -> BT*HS
             (long long)T_*HS_, (long long)BT_*HS_,     // B: same
             (long long)H_*T_*T_, (long long)T_*T_);    // C: b -> H*T*T, h -> T*T

        // masked softmax (reference quirk handled inside)
        softmax_kernel<<<B_*H_*T_, 256>>>(s);

        // av = softmax(s) @ v  -> av layout [B, T, H*HS]
        gemm(s, v, av, nullptr, T_, HS_, T_, T_, HS_, H_*HS_,
             false, false, false, B_*H_, H_,
             (long long)H_*T_*T_, (long long)T_*T_,
             (long long)T_*HS_, (long long)BT_*HS_,
             (long long)T_*H_*HS_, (long long)HS_);

        // x += av @ Wo[l]   (Wo[l] is a contiguous [H*HS, D] matrix)
        gemm(av, Wo + (long long)l*H_*HS_*D_, x, nullptr,
             BT_, D_, H_*HS_, H_*HS_, D_, D_, false, true, false);

        // ln2
        ln_kernel<<<BT_, 128>>>(x, ln2_g + l*D_, ln2_b + l*D_, h);

        // ffn
        gemm(h, W1 + (long long)l*D_*DFF_, ffn, b1 + l*DFF_,
             BT_, DFF_, D_, D_, DFF_, DFF_, false, false, true);
        gemm(ffn, W2 + (long long)l*DFF_*D_, x, b2 + l*D_,
             BT_, D_, DFF_, DFF_, D_, D_, false, true, false);
    }

    // final LN
    ln_kernel<<<BT_, 128>>>(x, lnf_g, lnf_b, h);

    // LM head: logits = h @ Wlm + blm
    gemm(h, Wlm, logits, blm, BT_, V_, D_, D_, V_, V_, false, false, false);

    // loss
    lossrow_kernel<<<BT_, 256>>>(logits, targets, rl);
    if (out_has_logits && (long long)out_size > NLOGITS) {
        lossreduce_kernel<<<1, 256>>>(rl, out + NLOGITS);
    } else if (!out_has_logits && out_size >= 1) {
        lossreduce_kernel<<<1, 256>>>(rl, out);
    }
}

// round 2
// speedup vs baseline: 1.1713x; 1.1713x over previous
#include <cuda_runtime.h>
#include <cuda_bf16.h>
#include <math.h>

// Problem dims
#define B_  4
#define T_  1024
#define V_  32000
#define D_  384
#define H_  6
#define HS_ 64
#define L_  6
#define DFF_ 1536
#define BT_ (B_*T_)
#define QKVW_ (3*H_*HS_)   // 1152
#define EPS_ 1e-5f
#define SCALE_ 0.125f

// ---------------- static scratch ----------------
__device__ float g_x[BT_*D_];
__device__ float g_h[BT_*D_];
__device__ float g_qkv[(size_t)BT_*QKVW_];
__device__ float g_wpack[(size_t)L_*D_*QKVW_];
__device__ float g_s[(size_t)B_*H_*T_*T_];
__device__ float g_av[BT_*D_];
__device__ float g_ffn[BT_*DFF_];
__device__ float g_rowloss[BT_];
__device__ float g_logits[(size_t)BT_*V_];

// ---------------- embed ----------------
__global__ void embed_kernel(const int* __restrict__ tok,
                             const float* __restrict__ tt,
                             const float* __restrict__ pt,
                             float* __restrict__ x)
{
    int idx = blockIdx.x * blockDim.x + threadIdx.x;
    if (idx >= BT_*D_) return;
    int bt = idx / D_;
    int d  = idx - bt * D_;
    int t  = bt % T_;
    x[idx] = tt[(size_t)tok[bt] * D_ + d] + pt[t * D_ + d];
}

// ---------------- pack Wq|Wk|Wv -> [L][D][1152] ----------------
__global__ void pack_qkv_kernel(const float* __restrict__ Wq,
                                const float* __restrict__ Wk,
                                const float* __restrict__ Wv,
                                float* __restrict__ P)
{
    int idx = blockIdx.x * blockDim.x + threadIdx.x;
    const int total = L_ * D_ * QKVW_;
    if (idx >= total) return;
    int l   = idx / (D_ * QKVW_);
    int rem = idx - l * (D_ * QKVW_);
    int d   = rem / QKVW_;
    int c   = rem - d * QKVW_;
    int grp = c / (H_*HS_);
    int hc  = c - grp * (H_*HS_);
    int h   = hc / HS_;
    int e   = hc - h * HS_;
    const float* W = (grp == 0) ? Wq : (grp == 1) ? Wk : Wv;
    P[idx] = W[((size_t)(l * H_ + h) * D_ + d) * HS_ + e];
}

// ---------------- layernorm ----------------
__global__ void ln_kernel(const float* __restrict__ x,
                          const float* __restrict__ g,
                          const float* __restrict__ b,
                          float* __restrict__ y)
{
    __shared__ float rs[128], rq[128];
    int row = blockIdx.x;
    int tid = threadIdx.x;
    const float* xr = x + (size_t)row * D_;
    float s = 0.f, q = 0.f;
    #pragma unroll
    for (int i = tid; i < D_; i += 128) { float v = xr[i]; s += v; q += v*v; }
    rs[tid] = s; rq[tid] = q;
    __syncthreads();
    for (int off = 64; off > 0; off >>= 1) {
        if (tid < off) { rs[tid] += rs[tid+off]; rq[tid] += rq[tid+off]; }
        __syncthreads();
    }
    float mean = rs[0] / D_;
    float var  = rq[0] / D_ - mean * mean;
    float inv  = rsqrtf(var + EPS_);
    float* yr = y + (size_t)row * D_;
    #pragma unroll
    for (int i = tid; i < D_; i += 128)
        yr[i] = (xr[i] - mean) * inv * g[i] + b[i];
}

// ---------------- tiled SGEMM: BMxBN tile, TMxTN microtile, 256 threads ----------------
// C[M,N] = A[M,K] * op(B) (+bias)(+C)(relu). TB: B is [N,K] row-major.
// z-batching: zq=z/zdiv, zr=z%zdiv; ptr += zq*s?d + zr*s?m.
// Requires: M%BM==0, N%BN==0, K%BK==0 (true for all shapes here).
template<int BM, int BN, int BK, int TM, int TN, int TB>
__global__ void __launch_bounds__(256, 2)
sgemm_kernel(const float* __restrict__ A,
             const float* __restrict__ B,
             float* __restrict__ C,
             const float* __restrict__ bias,
             int K, int lda, int ldb, int ldc,
             int accumulate, int relu, int zdiv,
             long long sAd, long long sAm,
             long long sBd, long long sBm,
             long long sCd, long long sCm)
{
    static_assert((BM/TM)*(BN/TN) == 256, "256 threads");
    __shared__ float As[BK][BM];
    __shared__ float Bs[BK][BN];

    int z  = blockIdx.z;
    int zq = z / zdiv;
    int zr = z - zq * zdiv;
    A += zq * sAd + (long long)zr * sAm;
    B += zq * sBd + (long long)zr * sBm;
    C += zq * sCd + (long long)zr * sCm;

    const int tid = threadIdx.x;
    const int tx = tid % (BN/TN);
    const int ty = tid / (BN/TN);
    const int row0 = blockIdx.y * BM;
    const int col0 = blockIdx.x * BN;

    float acc[TM][TN] = {};

    constexpr int A4  = BM*BK/4;
    constexpr int APT = A4/256;
    constexpr int B4  = BN*BK/4;
    constexpr int BPT = B4/256;

    for (int k0 = 0; k0 < K; k0 += BK) {
        // load A tile (transposed into As[k][m])
        #pragma unroll
        for (int i = 0; i < APT; i++) {
            int idx4 = tid + i*256;
            int m  = idx4 / (BK/4);
            int kq = idx4 % (BK/4);
            float4 a4 = *(const float4*)(A + (size_t)(row0+m)*lda + k0 + kq*4);
            As[kq*4+0][m] = a4.x;
            As[kq*4+1][m] = a4.y;
            As[kq*4+2][m] = a4.z;
            As[kq*4+3][m] = a4.w;
        }
        // load B tile
        if (!TB) {
            #pragma unroll
            for (int i = 0; i < BPT; i++) {
                int idx4 = tid + i*256;
                int kb = idx4 / (BN/4);
                int nq = idx4 % (BN/4);
                float4 b4 = *(const float4*)(B + (size_t)(k0+kb)*ldb + col0 + nq*4);
                *(float4*)&Bs[kb][nq*4] = b4;
            }
        } else {
            #pragma unroll
            for (int i = 0; i < BPT; i++) {
                int idx4 = tid + i*256;
                int n  = idx4 / (BK/4);
                int kq = idx4 % (BK/4);
                float4 b4 = *(const float4*)(B + (size_t)(col0+n)*ldb + k0 + kq*4);
                Bs[kq*4+0][n] = b4.x;
                Bs[kq*4+1][n] = b4.y;
                Bs[kq*4+2][n] = b4.z;
                Bs[kq*4+3][n] = b4.w;
            }
        }
        __syncthreads();

        #pragma unroll
        for (int kk = 0; kk < BK; kk++) {
            float a[TM], b[TN];
            #pragma unroll
            for (int i = 0; i < TM; i += 4)
                *(float4*)&a[i] = *(const float4*)&As[kk][ty*TM + i];
            #pragma unroll
            for (int j = 0; j < TN; j += 4)
                *(float4*)&b[j] = *(const float4*)&Bs[kk][tx*TN + j];
            #pragma unroll
            for (int i = 0; i < TM; i++)
                #pragma unroll
                for (int j = 0; j < TN; j++)
                    acc[i][j] = fmaf(a[i], b[j], acc[i][j]);
        }
        __syncthreads();
    }

    // epilogue
    #pragma unroll
    for (int i = 0; i < TM; i++) {
        int r = row0 + ty*TM + i;
        #pragma unroll
        for (int j0 = 0; j0 < TN; j0 += 4) {
            int c = col0 + tx*TN + j0;
            float4 v = *(float4*)&acc[i][j0];
            if (bias) {
                float4 bb = *(const float4*)(bias + c);
                v.x += bb.x; v.y += bb.y; v.z += bb.z; v.w += bb.w;
            }
            float* cp = C + (size_t)r * ldc + c;
            if (accumulate) {
                float4 cc = *(const float4*)cp;
                v.x += cc.x; v.y += cc.y; v.z += cc.z; v.w += cc.w;
            }
            if (relu) {
                v.x = fmaxf(v.x, 0.f); v.y = fmaxf(v.y, 0.f);
                v.z = fmaxf(v.z, 0.f); v.w = fmaxf(v.w, 0.f);
            }
            *(float4*)cp = v;
        }
    }
}

// ---------------- softmax (reference tril*scale quirk) ----------------
__global__ void softmax_kernel(float* __restrict__ S)
{
    __shared__ float red[256];
    size_t row = blockIdx.x;
    int t = (int)(row % T_);
    float* p = S + row * T_;
    int tid = threadIdx.x;

    float vals[4];
    float m = -1e30f;
    #pragma unroll
    for (int j = 0; j < 4; j++) {
        int s = tid + j * 256;
        float v = (s <= t) ? p[s] * SCALE_ : 0.0f;
        vals[j] = v;
        m = fmaxf(m, v);
    }
    red[tid] = m; __syncthreads();
    for (int off = 128; off > 0; off >>= 1) {
        if (tid < off) red[tid] = fmaxf(red[tid], red[tid+off]);
        __syncthreads();
    }
    m = red[0]; __syncthreads();

    float sum = 0.f;
    #pragma unroll
    for (int j = 0; j < 4; j++) { vals[j] = __expf(vals[j] - m); sum += vals[j]; }
    red[tid] = sum; __syncthreads();
    for (int off = 128; off > 0; off >>= 1) {
        if (tid < off) red[tid] += red[tid+off];
        __syncthreads();
    }
    float inv = 1.0f / red[0];
    #pragma unroll
    for (int j = 0; j < 4; j++) p[tid + j*256] = vals[j] * inv;
}

// ---------------- loss ----------------
__global__ void lossrow_kernel(const float* __restrict__ logits,
                               const int* __restrict__ tgt,
                               float* __restrict__ rowloss)
{
    __shared__ float red[256];
    int row = blockIdx.x;
    int tid = threadIdx.x;
    const float* p = logits + (size_t)row * V_;

    float m = -1e30f;
    for (int s = tid; s < V_; s += 256) m = fmaxf(m, p[s]);
    red[tid] = m; __syncthreads();
    for (int off = 128; off > 0; off >>= 1) {
        if (tid < off) red[tid] = fmaxf(red[tid], red[tid+off]);
        __syncthreads();
    }
    m = red[0]; __syncthreads();

    float sum = 0.f;
    for (int s = tid; s < V_; s += 256) sum += __expf(p[s] - m);
    red[tid] = sum; __syncthreads();
    for (int off = 128; off > 0; off >>= 1) {
        if (tid < off) red[tid] += red[tid+off];
        __syncthreads();
    }
    if (tid == 0) {
        float lse = m + logf(red[0]);
        rowloss[row] = lse - p[tgt[row]];
    }
}

__global__ void lossreduce_kernel(const float* __restrict__ rowloss,
                                  float* __restrict__ out)
{
    __shared__ float red[256];
    int tid = threadIdx.x;
    float s = 0.f;
    for (int i = tid; i < BT_; i += 256) s += rowloss[i];
    red[tid] = s; __syncthreads();
    for (int off = 128; off > 0; off >>= 1) {
        if (tid < off) red[tid] += red[tid+off];
        __syncthreads();
    }
    if (tid == 0) out[0] = red[0] / (float)BT_;
}

// ---------------- host ----------------
static float* sym(const void* s)
{
    void* p = nullptr;
    cudaGetSymbolAddress(&p, s);
    return (float*)p;
}

struct GemmArgs {
    const float *A, *B; float* C; const float* bias;
    int M, N, K, lda, ldb, ldc;
    bool acc, relu;
    int Z, zdiv;
    long long sAd, sAm, sBd, sBm, sCd, sCm;
};

static void gemm128x128(const GemmArgs& g, bool tb)
{
    dim3 grid(g.N / 128, g.M / 128, g.Z);
    if (!tb)
        sgemm_kernel<128,128,16,8,8,0><<<grid, 256>>>(
            g.A, g.B, g.C, g.bias, g.K, g.lda, g.ldb, g.ldc,
            g.acc, g.relu, g.zdiv, g.sAd, g.sAm, g.sBd, g.sBm, g.sCd, g.sCm);
    else
        sgemm_kernel<128,128,16,8,8,1><<<grid, 256>>>(
            g.A, g.B, g.C, g.bias, g.K, g.lda, g.ldb, g.ldc,
            g.acc, g.relu, g.zdiv, g.sAd, g.sAm, g.sBd, g.sBm, g.sCd, g.sCm);
}

static void gemm128x64(const GemmArgs& g)
{
    dim3 grid(g.N / 64, g.M / 128, g.Z);
    sgemm_kernel<128,64,16,8,4,0><<<grid, 256>>>(
        g.A, g.B, g.C, g.bias, g.K, g.lda, g.ldb, g.ldc,
        g.acc, g.relu, g.zdiv, g.sAd, g.sAm, g.sBd, g.sBm, g.sCd, g.sCm);
}

extern "C" void kernel_launch(void* const* d_in, const int* in_sizes, int n_in,
                              void* d_out, int out_size)
{
    const int*   token_ids = (const int*)d_in[0];
    const int*   targets   = (const int*)d_in[1];
    const float* tok_table = (const float*)d_in[2];
    const float* pos_table = (const float*)d_in[3];
    const float* ln1_g = (const float*)d_in[4];
    const float* ln1_b = (const float*)d_in[5];
    const float* Wq = (const float*)d_in[6];
    const float* Wk = (const float*)d_in[7];
    const float* Wv = (const float*)d_in[8];
    const float* Wo = (const float*)d_in[9];
    const float* ln2_g = (const float*)d_in[10];
    const float* ln2_b = (const float*)d_in[11];
    const float* W1 = (const float*)d_in[12];
    const float* b1 = (const float*)d_in[13];
    const float* W2 = (const float*)d_in[14];
    const float* b2 = (const float*)d_in[15];
    const float* lnf_g = (const float*)d_in[16];
    const float* lnf_b = (const float*)d_in[17];
    const float* Wlm = (const float*)d_in[18];
    const float* blm = (const float*)d_in[19];

    float* x    = sym(g_x);
    float* h    = sym(g_h);
    float* qkv  = sym(g_qkv);
    float* wp   = sym(g_wpack);
    float* s    = sym(g_s);
    float* av   = sym(g_av);
    float* ffn  = sym(g_ffn);
    float* rl   = sym(g_rowloss);

    const long long NLOGITS = (long long)BT_ * V_;
    float* out = (float*)d_out;
    bool out_has_logits = ((long long)out_size >= NLOGITS);
    float* logits = out_has_logits ? out : sym(g_logits);

    // embed + weight pack
    embed_kernel<<<(BT_*D_ + 255)/256, 256>>>(token_ids, tok_table, pos_table, x);
    {
        int total = L_ * D_ * QKVW_;
        pack_qkv_kernel<<<(total + 255)/256, 256>>>(Wq, Wk, Wv, wp);
    }

    for (int l = 0; l < L_; l++) {
        ln_kernel<<<BT_, 128>>>(x, ln1_g + l*D_, ln1_b + l*D_, h);

        // fused QKV: [BT,384] @ [384,1152] -> qkv [BT,1152]
        {
            GemmArgs g{h, wp + (long long)l*D_*QKVW_, qkv, nullptr,
                       BT_, QKVW_, D_, D_, QKVW_, QKVW_,
                       false, false, 1, 1, 0,0,0,0,0,0};
            gemm128x128(g, false);
        }

        // scores = q @ k^T (z = b*H + h)
        {
            GemmArgs g{qkv, qkv + H_*HS_, s, nullptr,
                       T_, T_, HS_, QKVW_, QKVW_, T_,
                       false, false, B_*H_, H_,
                       (long long)T_*QKVW_, HS_,
                       (long long)T_*QKVW_, HS_,
                       (long long)H_*T_*T_, (long long)T_*T_};
            gemm128x128(g, true);
        }

        softmax_kernel<<<B_*H_*T_, 256>>>(s);

        // av = attn @ v  -> [B,T,H*HS]
        {
            GemmArgs g{s, qkv + 2*H_*HS_, av, nullptr,
                       T_, HS_, T_, T_, QKVW_, D_,
                       false, false, B_*H_, H_,
                       (long long)H_*T_*T_, (long long)T_*T_,
                       (long long)T_*QKVW_, HS_,
                       (long long)T_*D_, HS_};
            gemm128x64(g);
        }

        // x += av @ Wo[l]
        {
            GemmArgs g{av, Wo + (long long)l*H_*HS_*D_, x, nullptr,
                       BT_, D_, H_*HS_, H_*HS_, D_, D_,
                       true, false, 1, 1, 0,0,0,0,0,0};
            gemm128x128(g, false);
        }

        ln_kernel<<<BT_, 128>>>(x, ln2_g + l*D_, ln2_b + l*D_, h);

        // ffn
        {
            GemmArgs g{h, W1 + (long long)l*D_*DFF_, ffn, b1 + l*DFF_,
                       BT_, DFF_, D_, D_, DFF_, DFF_,
                       false, true, 1, 1, 0,0,0,0,0,0};
            gemm128x128(g, false);
        }
        {
            GemmArgs g{ffn, W2 + (long long)l*DFF_*D_, x, b2 + l*D_,
                       BT_, D_, DFF_, DFF_, D_, D_,
                       true, false, 1, 1, 0,0,0,0,0,0};
            gemm128x128(g, false);
        }
    }

    ln_kernel<<<BT_, 128>>>(x, lnf_g, lnf_b, h);

    // LM head
    {
        GemmArgs g{h, Wlm, logits, blm,
                   BT_, V_, D_, D_, V_, V_,
                   false, false, 1, 1, 0,0,0,0,0,0};
        gemm128x128(g, false);
    }

    lossrow_kernel<<<BT_, 256>>>(logits, targets, rl);
    if (out_has_logits && (long long)out_size > NLOGITS) {
        lossreduce_kernel<<<1, 256>>>(rl, out + NLOGITS);
    } else if (!out_has_logits && out_size >= 1) {
        lossreduce_kernel<<<1, 256>>>(rl, out);
    }
}

// round 3
// speedup vs baseline: 2.0543x; 1.7539x over previous
#include <cuda_runtime.h>
#include <cuda_bf16.h>
#include <math.h>
#include <stdint.h>

// Problem dims
#define B_  4
#define T_  1024
#define V_  32000
#define D_  384
#define H_  6
#define HS_ 64
#define L_  6
#define DFF_ 1536
#define BT_ (B_*T_)
#define QKVW_ (3*H_*HS_)   // 1152
#define EPS_ 1e-5f
#define SCALE_ 0.125f

// ---------------- static scratch ----------------
__device__ float g_x[BT_*D_];
__device__ float g_h[BT_*D_];
__device__ float g_qkv[(size_t)BT_*QKVW_];
__device__ float g_wpack[(size_t)L_*D_*QKVW_];
__device__ float g_s[(size_t)B_*H_*T_*T_];
__device__ float g_av[BT_*D_];
__device__ float g_ffn[BT_*DFF_];
__device__ float g_rowloss[BT_];
__device__ float g_logits[(size_t)BT_*V_];

// ---------------- embed ----------------
__global__ void embed_kernel(const int* __restrict__ tok,
                             const float* __restrict__ tt,
                             const float* __restrict__ pt,
                             float* __restrict__ x)
{
    int idx = blockIdx.x * blockDim.x + threadIdx.x;
    if (idx >= BT_*D_) return;
    int bt = idx / D_;
    int d  = idx - bt * D_;
    int t  = bt % T_;
    x[idx] = tt[(size_t)tok[bt] * D_ + d] + pt[t * D_ + d];
}

// ---------------- pack Wq|Wk|Wv -> [L][D][1152] ----------------
__global__ void pack_qkv_kernel(const float* __restrict__ Wq,
                                const float* __restrict__ Wk,
                                const float* __restrict__ Wv,
                                float* __restrict__ P)
{
    int idx = blockIdx.x * blockDim.x + threadIdx.x;
    const int total = L_ * D_ * QKVW_;
    if (idx >= total) return;
    int l   = idx / (D_ * QKVW_);
    int rem = idx - l * (D_ * QKVW_);
    int d   = rem / QKVW_;
    int c   = rem - d * QKVW_;
    int grp = c / (H_*HS_);
    int hc  = c - grp * (H_*HS_);
    int h   = hc / HS_;
    int e   = hc - h * HS_;
    const float* W = (grp == 0) ? Wq : (grp == 1) ? Wk : Wv;
    P[idx] = W[((size_t)(l * H_ + h) * D_ + d) * HS_ + e];
}

// ---------------- layernorm ----------------
__global__ void ln_kernel(const float* __restrict__ x,
                          const float* __restrict__ g,
                          const float* __restrict__ b,
                          float* __restrict__ y)
{
    __shared__ float rs[128], rq[128];
    int row = blockIdx.x;
    int tid = threadIdx.x;
    const float* xr = x + (size_t)row * D_;
    float s = 0.f, q = 0.f;
    #pragma unroll
    for (int i = tid; i < D_; i += 128) { float v = xr[i]; s += v; q += v*v; }
    rs[tid] = s; rq[tid] = q;
    __syncthreads();
    for (int off = 64; off > 0; off >>= 1) {
        if (tid < off) { rs[tid] += rs[tid+off]; rq[tid] += rq[tid+off]; }
        __syncthreads();
    }
    float mean = rs[0] / D_;
    float var  = rq[0] / D_ - mean * mean;
    float inv  = rsqrtf(var + EPS_);
    float* yr = y + (size_t)row * D_;
    #pragma unroll
    for (int i = tid; i < D_; i += 128)
        yr[i] = (xr[i] - mean) * inv * g[i] + b[i];
}

// ---------------- tf32 helpers ----------------
__device__ __forceinline__ float tf32r(float x)
{
    asm("cvt.rna.tf32.f32 %0, %0;" : "+f"(x));
    return x;
}

__device__ __forceinline__ void mma_tf32(float c[4], const uint32_t a[4], const uint32_t b[2])
{
    asm volatile(
        "mma.sync.aligned.m16n8k8.row.col.f32.tf32.tf32.f32 "
        "{%0,%1,%2,%3}, {%4,%5,%6,%7}, {%8,%9}, {%0,%1,%2,%3};"
        : "+f"(c[0]), "+f"(c[1]), "+f"(c[2]), "+f"(c[3])
        : "r"(a[0]), "r"(a[1]), "r"(a[2]), "r"(a[3]), "r"(b[0]), "r"(b[1]));
}

// ---------------- tensor-core GEMM (tf32 mma.sync) ----------------
// C[M,N] = A[M,K] * op(B) (+bias)(+C)(relu). TB: B is [N,K] row-major (NT).
// z-batching: zq=z/zdiv, zr=z%zdiv; ptr += zq*s?d + zr*s?m.
// Requires M%BM==0, N%BN==0, K%BK==0.
template<int BM, int BN, int BK, int WM, int WN, int TB>
__global__ void __launch_bounds__(256, 2)
tgemm_kernel(const float* __restrict__ A,
             const float* __restrict__ B,
             float* __restrict__ C,
             const float* __restrict__ bias,
             int K, int lda, int ldb, int ldc,
             int accumulate, int relu, int zdiv,
             long long sAd, long long sAm,
             long long sBd, long long sBm,
             long long sCd, long long sCm)
{
    constexpr int MT = WM / 16;
    constexpr int NT = WN / 8;
    constexpr int WARPS_N = BN / WN;
    constexpr int WARPS_M = BM / WM;
    static_assert(WARPS_M * WARPS_N == 8, "8 warps");
    constexpr int LDA_S = BM + 4;
    constexpr int LDB_S = BN + 4;

    __shared__ float As[BK][LDA_S];
    __shared__ float Bs[BK][LDB_S];

    int z  = blockIdx.z;
    int zq = z / zdiv;
    int zr = z - zq * zdiv;
    A += zq * sAd + (long long)zr * sAm;
    B += zq * sBd + (long long)zr * sBm;
    C += zq * sCd + (long long)zr * sCm;

    const int tid  = threadIdx.x;
    const int lane = tid & 31;
    const int wid  = tid >> 5;
    const int wm   = wid / WARPS_N;
    const int wn   = wid % WARPS_N;
    const int gid  = lane >> 2;
    const int tig  = lane & 3;

    const int row0 = blockIdx.y * BM;
    const int col0 = blockIdx.x * BN;

    float acc[MT][NT][4] = {};

    constexpr int APT = (BM*BK/4) / 256;
    constexpr int BPT = (BN*BK/4) / 256;

    for (int k0 = 0; k0 < K; k0 += BK) {
        // stage A (transposed to As[k][m]), rounding to tf32
        #pragma unroll
        for (int i = 0; i < APT; i++) {
            int idx4 = tid + i*256;
            int m  = idx4 / (BK/4);
            int kq = idx4 % (BK/4);
            float4 a4 = *(const float4*)(A + (size_t)(row0+m)*lda + k0 + kq*4);
            As[kq*4+0][m] = tf32r(a4.x);
            As[kq*4+1][m] = tf32r(a4.y);
            As[kq*4+2][m] = tf32r(a4.z);
            As[kq*4+3][m] = tf32r(a4.w);
        }
        // stage B into Bs[k][n]
        if (!TB) {
            #pragma unroll
            for (int i = 0; i < BPT; i++) {
                int idx4 = tid + i*256;
                int kb = idx4 / (BN/4);
                int nq = idx4 % (BN/4);
                float4 b4 = *(const float4*)(B + (size_t)(k0+kb)*ldb + col0 + nq*4);
                Bs[kb][nq*4+0] = tf32r(b4.x);
                Bs[kb][nq*4+1] = tf32r(b4.y);
                Bs[kb][nq*4+2] = tf32r(b4.z);
                Bs[kb][nq*4+3] = tf32r(b4.w);
            }
        } else {
            #pragma unroll
            for (int i = 0; i < BPT; i++) {
                int idx4 = tid + i*256;
                int n  = idx4 / (BK/4);
                int kq = idx4 % (BK/4);
                float4 b4 = *(const float4*)(B + (size_t)(col0+n)*ldb + k0 + kq*4);
                Bs[kq*4+0][n] = tf32r(b4.x);
                Bs[kq*4+1][n] = tf32r(b4.y);
                Bs[kq*4+2][n] = tf32r(b4.z);
                Bs[kq*4+3][n] = tf32r(b4.w);
            }
        }
        __syncthreads();

        #pragma unroll
        for (int ks = 0; ks < BK/8; ks++) {
            uint32_t af[MT][4];
            uint32_t bf[NT][2];
            #pragma unroll
            for (int mt = 0; mt < MT; mt++) {
                int m0 = wm*WM + mt*16;
                af[mt][0] = __float_as_uint(As[ks*8 + tig    ][m0 + gid    ]);
                af[mt][1] = __float_as_uint(As[ks*8 + tig    ][m0 + gid + 8]);
                af[mt][2] = __float_as_uint(As[ks*8 + tig + 4][m0 + gid    ]);
                af[mt][3] = __float_as_uint(As[ks*8 + tig + 4][m0 + gid + 8]);
            }
            #pragma unroll
            for (int nt = 0; nt < NT; nt++) {
                int n0 = wn*WN + nt*8;
                bf[nt][0] = __float_as_uint(Bs[ks*8 + tig    ][n0 + gid]);
                bf[nt][1] = __float_as_uint(Bs[ks*8 + tig + 4][n0 + gid]);
            }
            #pragma unroll
            for (int mt = 0; mt < MT; mt++)
                #pragma unroll
                for (int nt = 0; nt < NT; nt++)
                    mma_tf32(acc[mt][nt], af[mt], bf[nt]);
        }
        __syncthreads();
    }

    // epilogue: thread owns (r, c), (r, c+1), (r+8, c), (r+8, c+1) per tile
    #pragma unroll
    for (int mt = 0; mt < MT; mt++) {
        #pragma unroll
        for (int nt = 0; nt < NT; nt++) {
            int r = row0 + wm*WM + mt*16 + gid;
            int c = col0 + wn*WN + nt*8 + tig*2;
            float2 v0 = make_float2(acc[mt][nt][0], acc[mt][nt][1]);
            float2 v1 = make_float2(acc[mt][nt][2], acc[mt][nt][3]);
            if (bias) {
                float2 bb = *(const float2*)(bias + c);
                v0.x += bb.x; v0.y += bb.y;
                v1.x += bb.x; v1.y += bb.y;
            }
            float* p0 = C + (size_t)r * ldc + c;
            float* p1 = C + (size_t)(r+8) * ldc + c;
            if (accumulate) {
                float2 c0 = *(const float2*)p0;
                float2 c1 = *(const float2*)p1;
                v0.x += c0.x; v0.y += c0.y;
                v1.x += c1.x; v1.y += c1.y;
            }
            if (relu) {
                v0.x = fmaxf(v0.x, 0.f); v0.y = fmaxf(v0.y, 0.f);
                v1.x = fmaxf(v1.x, 0.f); v1.y = fmaxf(v1.y, 0.f);
            }
            *(float2*)p0 = v0;
            *(float2*)p1 = v1;
        }
    }
}

// ---------------- softmax (reference tril*scale quirk) ----------------
__global__ void softmax_kernel(float* __restrict__ S)
{
    __shared__ float red[256];
    size_t row = blockIdx.x;
    int t = (int)(row % T_);
    float* p = S + row * T_;
    int tid = threadIdx.x;

    float vals[4];
    float m = -1e30f;
    #pragma unroll
    for (int j = 0; j < 4; j++) {
        int s = tid + j * 256;
        float v = (s <= t) ? p[s] * SCALE_ : 0.0f;
        vals[j] = v;
        m = fmaxf(m, v);
    }
    red[tid] = m; __syncthreads();
    for (int off = 128; off > 0; off >>= 1) {
        if (tid < off) red[tid] = fmaxf(red[tid], red[tid+off]);
        __syncthreads();
    }
    m = red[0]; __syncthreads();

    float sum = 0.f;
    #pragma unroll
    for (int j = 0; j < 4; j++) { vals[j] = __expf(vals[j] - m); sum += vals[j]; }
    red[tid] = sum; __syncthreads();
    for (int off = 128; off > 0; off >>= 1) {
        if (tid < off) red[tid] += red[tid+off];
        __syncthreads();
    }
    float inv = 1.0f / red[0];
    #pragma unroll
    for (int j = 0; j < 4; j++) p[tid + j*256] = vals[j] * inv;
}

// ---------------- loss ----------------
__global__ void lossrow_kernel(const float* __restrict__ logits,
                               const int* __restrict__ tgt,
                               float* __restrict__ rowloss)
{
    __shared__ float red[256];
    int row = blockIdx.x;
    int tid = threadIdx.x;
    const float* p = logits + (size_t)row * V_;

    float m = -1e30f;
    for (int s = tid; s < V_; s += 256) m = fmaxf(m, p[s]);
    red[tid] = m; __syncthreads();
    for (int off = 128; off > 0; off >>= 1) {
        if (tid < off) red[tid] = fmaxf(red[tid], red[tid+off]);
        __syncthreads();
    }
    m = red[0]; __syncthreads();

    float sum = 0.f;
    for (int s = tid; s < V_; s += 256) sum += __expf(p[s] - m);
    red[tid] = sum; __syncthreads();
    for (int off = 128; off > 0; off >>= 1) {
        if (tid < off) red[tid] += red[tid+off];
        __syncthreads();
    }
    if (tid == 0) {
        float lse = m + logf(red[0]);
        rowloss[row] = lse - p[tgt[row]];
    }
}

__global__ void lossreduce_kernel(const float* __restrict__ rowloss,
                                  float* __restrict__ out)
{
    __shared__ float red[256];
    int tid = threadIdx.x;
    float s = 0.f;
    for (int i = tid; i < BT_; i += 256) s += rowloss[i];
    red[tid] = s; __syncthreads();
    for (int off = 128; off > 0; off >>= 1) {
        if (tid < off) red[tid] += red[tid+off];
        __syncthreads();
    }
    if (tid == 0) out[0] = red[0] / (float)BT_;
}

// ---------------- host ----------------
static float* sym(const void* s)
{
    void* p = nullptr;
    cudaGetSymbolAddress(&p, s);
    return (float*)p;
}

struct GemmArgs {
    const float *A, *B; float* C; const float* bias;
    int M, N, K, lda, ldb, ldc;
    bool acc, relu;
    int Z, zdiv;
    long long sAd, sAm, sBd, sBm, sCd, sCm;
};

// 128x128 tile, warp grid 2x4, warp tile 64x32
static void gemm128x128(const GemmArgs& g, bool tb)
{
    dim3 grid(g.N / 128, g.M / 128, g.Z);
    if (!tb)
        tgemm_kernel<128,128,16,64,32,0><<<grid, 256>>>(
            g.A, g.B, g.C, g.bias, g.K, g.lda, g.ldb, g.ldc,
            g.acc, g.relu, g.zdiv, g.sAd, g.sAm, g.sBd, g.sBm, g.sCd, g.sCm);
    else
        tgemm_kernel<128,128,16,64,32,1><<<grid, 256>>>(
            g.A, g.B, g.C, g.bias, g.K, g.lda, g.ldb, g.ldc,
            g.acc, g.relu, g.zdiv, g.sAd, g.sAm, g.sBd, g.sBm, g.sCd, g.sCm);
}

// 128x64 tile, warp grid 4x2, warp tile 32x32
static void gemm128x64(const GemmArgs& g)
{
    dim3 grid(g.N / 64, g.M / 128, g.Z);
    tgemm_kernel<128,64,16,32,32,0><<<grid, 256>>>(
        g.A, g.B, g.C, g.bias, g.K, g.lda, g.ldb, g.ldc,
        g.acc, g.relu, g.zdiv, g.sAd, g.sAm, g.sBd, g.sBm, g.sCd, g.sCm);
}

extern "C" void kernel_launch(void* const* d_in, const int* in_sizes, int n_in,
                              void* d_out, int out_size)
{
    const int*   token_ids = (const int*)d_in[0];
    const int*   targets   = (const int*)d_in[1];
    const float* tok_table = (const float*)d_in[2];
    const float* pos_table = (const float*)d_in[3];
    const float* ln1_g = (const float*)d_in[4];
    const float* ln1_b = (const float*)d_in[5];
    const float* Wq = (const float*)d_in[6];
    const float* Wk = (const float*)d_in[7];
    const float* Wv = (const float*)d_in[8];
    const float* Wo = (const float*)d_in[9];
    const float* ln2_g = (const float*)d_in[10];
    const float* ln2_b = (const float*)d_in[11];
    const float* W1 = (const float*)d_in[12];
    const float* b1 = (const float*)d_in[13];
    const float* W2 = (const float*)d_in[14];
    const float* b2 = (const float*)d_in[15];
    const float* lnf_g = (const float*)d_in[16];
    const float* lnf_b = (const float*)d_in[17];
    const float* Wlm = (const float*)d_in[18];
    const float* blm = (const float*)d_in[19];

    float* x    = sym(g_x);
    float* h    = sym(g_h);
    float* qkv  = sym(g_qkv);
    float* wp   = sym(g_wpack);
    float* s    = sym(g_s);
    float* av   = sym(g_av);
    float* ffn  = sym(g_ffn);
    float* rl   = sym(g_rowloss);

    const long long NLOGITS = (long long)BT_ * V_;
    float* out = (float*)d_out;
    bool out_has_logits = ((long long)out_size >= NLOGITS);
    float* logits = out_has_logits ? out : sym(g_logits);

    // embed + weight pack
    embed_kernel<<<(BT_*D_ + 255)/256, 256>>>(token_ids, tok_table, pos_table, x);
    {
        int total = L_ * D_ * QKVW_;
        pack_qkv_kernel<<<(total + 255)/256, 256>>>(Wq, Wk, Wv, wp);
    }

    for (int l = 0; l < L_; l++) {
        ln_kernel<<<BT_, 128>>>(x, ln1_g + l*D_, ln1_b + l*D_, h);

        // fused QKV: [BT,384] @ [384,1152] -> qkv [BT,1152]
        {
            GemmArgs g{h, wp + (long long)l*D_*QKVW_, qkv, nullptr,
                       BT_, QKVW_, D_, D_, QKVW_, QKVW_,
                       false, false, 1, 1, 0,0,0,0,0,0};
            gemm128x128(g, false);
        }

        // scores = q @ k^T (z = b*H + h)
        {
            GemmArgs g{qkv, qkv + H_*HS_, s, nullptr,
                       T_, T_, HS_, QKVW_, QKVW_, T_,
                       false, false, B_*H_, H_,
                       (long long)T_*QKVW_, HS_,
                       (long long)T_*QKVW_, HS_,
                       (long long)H_*T_*T_, (long long)T_*T_};
            gemm128x128(g, true);
        }

        softmax_kernel<<<B_*H_*T_, 256>>>(s);

        // av = attn @ v  -> [B,T,H*HS]
        {
            GemmArgs g{s, qkv + 2*H_*HS_, av, nullptr,
                       T_, HS_, T_, T_, QKVW_, D_,
                       false, false, B_*H_, H_,
                       (long long)H_*T_*T_, (long long)T_*T_,
                       (long long)T_*QKVW_, HS_,
                       (long long)T_*D_, HS_};
            gemm128x64(g);
        }

        // x += av @ Wo[l]
        {
            GemmArgs g{av, Wo + (long long)l*H_*HS_*D_, x, nullptr,
                       BT_, D_, H_*HS_, H_*HS_, D_, D_,
                       true, false, 1, 1, 0,0,0,0,0,0};
            gemm128x128(g, false);
        }

        ln_kernel<<<BT_, 128>>>(x, ln2_g + l*D_, ln2_b + l*D_, h);

        // ffn
        {
            GemmArgs g{h, W1 + (long long)l*D_*DFF_, ffn, b1 + l*DFF_,
                       BT_, DFF_, D_, D_, DFF_, DFF_,
                       false, true, 1, 1, 0,0,0,0,0,0};
            gemm128x128(g, false);
        }
        {
            GemmArgs g{ffn, W2 + (long long)l*DFF_*D_, x, b2 + l*D_,
                       BT_, D_, DFF_, DFF_, D_, D_,
                       true, false, 1, 1, 0,0,0,0,0,0};
            gemm128x128(g, false);
        }
    }

    ln_kernel<<<BT_, 128>>>(x, lnf_g, lnf_b, h);

    // LM head
    {
        GemmArgs g{h, Wlm, logits, blm,
                   BT_, V_, D_, D_, V_, V_,
                   false, false, 1, 1, 0,0,0,0,0,0};
        gemm128x128(g, false);
    }

    lossrow_kernel<<<BT_, 256>>>(logits, targets, rl);
    if (out_has_logits && (long long)out_size > NLOGITS) {
        lossreduce_kernel<<<1, 256>>>(rl, out + NLOGITS);
    } else if (!out_has_logits && out_size >= 1) {
        lossreduce_kernel<<<1, 256>>>(rl, out);
    }
}

// round 4
// speedup vs baseline: 2.4134x; 1.1748x over previous
#include <cuda_runtime.h>
#include <cuda_bf16.h>
#include <math.h>
#include <stdint.h>

// Problem dims
#define B_  4
#define T_  1024
#define V_  32000
#define D_  384
#define H_  6
#define HS_ 64
#define L_  6
#define DFF_ 1536
#define BT_ (B_*T_)
#define QKVW_ (3*H_*HS_)   // 1152
#define EPS_ 1e-5f
#define SCALE_ 0.125f

// ---------------- static scratch ----------------
__device__ float g_x[BT_*D_];
__device__ float g_h[BT_*D_];
__device__ float g_qkv[(size_t)BT_*QKVW_];
__device__ float g_wpack[(size_t)L_*D_*QKVW_];
__device__ float g_s[(size_t)B_*H_*T_*T_];
__device__ float g_av[BT_*D_];
__device__ float g_ffn[BT_*DFF_];
__device__ float g_rowloss[BT_];
__device__ float g_logits[(size_t)BT_*V_];

// ---------------- embed ----------------
__global__ void embed_kernel(const int* __restrict__ tok,
                             const float* __restrict__ tt,
                             const float* __restrict__ pt,
                             float* __restrict__ x)
{
    int idx = blockIdx.x * blockDim.x + threadIdx.x;
    if (idx >= BT_*D_) return;
    int bt = idx / D_;
    int d  = idx - bt * D_;
    int t  = bt % T_;
    x[idx] = tt[(size_t)tok[bt] * D_ + d] + pt[t * D_ + d];
}

// ---------------- pack Wq|Wk|Wv -> [L][D][1152] ----------------
__global__ void pack_qkv_kernel(const float* __restrict__ Wq,
                                const float* __restrict__ Wk,
                                const float* __restrict__ Wv,
                                float* __restrict__ P)
{
    int idx = blockIdx.x * blockDim.x + threadIdx.x;
    const int total = L_ * D_ * QKVW_;
    if (idx >= total) return;
    int l   = idx / (D_ * QKVW_);
    int rem = idx - l * (D_ * QKVW_);
    int d   = rem / QKVW_;
    int c   = rem - d * QKVW_;
    int grp = c / (H_*HS_);
    int hc  = c - grp * (H_*HS_);
    int h   = hc / HS_;
    int e   = hc - h * HS_;
    const float* W = (grp == 0) ? Wq : (grp == 1) ? Wk : Wv;
    P[idx] = W[((size_t)(l * H_ + h) * D_ + d) * HS_ + e];
}

// ---------------- layernorm ----------------
__global__ void ln_kernel(const float* __restrict__ x,
                          const float* __restrict__ g,
                          const float* __restrict__ b,
                          float* __restrict__ y)
{
    __shared__ float rs[128], rq[128];
    int row = blockIdx.x;
    int tid = threadIdx.x;
    const float* xr = x + (size_t)row * D_;
    float s = 0.f, q = 0.f;
    #pragma unroll
    for (int i = tid; i < D_; i += 128) { float v = xr[i]; s += v; q += v*v; }
    rs[tid] = s; rq[tid] = q;
    __syncthreads();
    for (int off = 64; off > 0; off >>= 1) {
        if (tid < off) { rs[tid] += rs[tid+off]; rq[tid] += rq[tid+off]; }
        __syncthreads();
    }
    float mean = rs[0] / D_;
    float var  = rq[0] / D_ - mean * mean;
    float inv  = rsqrtf(var + EPS_);
    float* yr = y + (size_t)row * D_;
    #pragma unroll
    for (int i = tid; i < D_; i += 128)
        yr[i] = (xr[i] - mean) * inv * g[i] + b[i];
}

// ---------------- tf32 helpers ----------------
__device__ __forceinline__ float tf32r(float x)
{
    asm("cvt.rna.tf32.f32 %0, %0;" : "+f"(x));
    return x;
}

__device__ __forceinline__ void mma_tf32(float c[4], const uint32_t a[4], const uint32_t b[2])
{
    asm volatile(
        "mma.sync.aligned.m16n8k8.row.col.f32.tf32.tf32.f32 "
        "{%0,%1,%2,%3}, {%4,%5,%6,%7}, {%8,%9}, {%0,%1,%2,%3};"
        : "+f"(c[0]), "+f"(c[1]), "+f"(c[2]), "+f"(c[3])
        : "r"(a[0]), "r"(a[1]), "r"(a[2]), "r"(a[3]), "r"(b[0]), "r"(b[1]));
}

// ---------------- double-buffered tensor-core GEMM (tf32 mma.sync) ----------------
// C[M,N] = A[M,K] * op(B) (+bias)(+C)(relu). TB: B is [N,K] row-major (NT).
// z-batching: zq=z/zdiv, zr=z%zdiv; ptr += zq*s?d + zr*s?m.
// Requires M%BM==0, N%BN==0, K%BK==0.
template<int BM, int BN, int BK, int WM, int WN, int TB>
__global__ void __launch_bounds__(256, 2)
tgemm_kernel(const float* __restrict__ A,
             const float* __restrict__ B,
             float* __restrict__ C,
             const float* __restrict__ bias,
             int K, int lda, int ldb, int ldc,
             int accumulate, int relu, int zdiv,
             long long sAd, long long sAm,
             long long sBd, long long sBm,
             long long sCd, long long sCm)
{
    constexpr int MT = WM / 16;
    constexpr int NT = WN / 8;
    constexpr int WARPS_N = BN / WN;
    constexpr int WARPS_M = BM / WM;
    static_assert(WARPS_M * WARPS_N == 8, "8 warps");
    constexpr int LDA_S = BM + 4;
    constexpr int LDB_S = BN + 4;
    constexpr int APT = (BM*BK/4) / 256;
    constexpr int BPT = (BN*BK/4) / 256;

    __shared__ float As[2][BK][LDA_S];
    __shared__ float Bs[2][BK][LDB_S];

    int z  = blockIdx.z;
    int zq = z / zdiv;
    int zr = z - zq * zdiv;
    A += zq * sAd + (long long)zr * sAm;
    B += zq * sBd + (long long)zr * sBm;
    C += zq * sCd + (long long)zr * sCm;

    const int tid  = threadIdx.x;
    const int lane = tid & 31;
    const int wid  = tid >> 5;
    const int wm   = wid / WARPS_N;
    const int wn   = wid % WARPS_N;
    const int gid  = lane >> 2;
    const int tig  = lane & 3;

    const int row0 = blockIdx.y * BM;
    const int col0 = blockIdx.x * BN;

    float acc[MT][NT][4] = {};

    float4 pa[APT], pb[BPT];

    // fixed per-thread staging coordinates
    int a_m[APT], a_kq[APT];
    #pragma unroll
    for (int i = 0; i < APT; i++) {
        int idx4 = tid + i*256;
        a_m[i]  = idx4 / (BK/4);
        a_kq[i] = idx4 % (BK/4);
    }
    int b_r[BPT], b_c[BPT];   // NN: (k-row, n-col4) ; TB: (n-row, k-col4)
    #pragma unroll
    for (int i = 0; i < BPT; i++) {
        int idx4 = tid + i*256;
        if (!TB) { b_r[i] = idx4 / (BN/4); b_c[i] = idx4 % (BN/4); }
        else     { b_r[i] = idx4 / (BK/4); b_c[i] = idx4 % (BK/4); }
    }

    auto LDG_TILE = [&](int k0) {
        #pragma unroll
        for (int i = 0; i < APT; i++)
            pa[i] = *(const float4*)(A + (size_t)(row0 + a_m[i]) * lda + k0 + a_kq[i]*4);
        if (!TB) {
            #pragma unroll
            for (int i = 0; i < BPT; i++)
                pb[i] = *(const float4*)(B + (size_t)(k0 + b_r[i]) * ldb + col0 + b_c[i]*4);
        } else {
            #pragma unroll
            for (int i = 0; i < BPT; i++)
                pb[i] = *(const float4*)(B + (size_t)(col0 + b_r[i]) * ldb + k0 + b_c[i]*4);
        }
    };

    auto STS_TILE = [&](int buf) {
        #pragma unroll
        for (int i = 0; i < APT; i++) {
            int m = a_m[i], kq = a_kq[i];
            As[buf][kq*4+0][m] = tf32r(pa[i].x);
            As[buf][kq*4+1][m] = tf32r(pa[i].y);
            As[buf][kq*4+2][m] = tf32r(pa[i].z);
            As[buf][kq*4+3][m] = tf32r(pa[i].w);
        }
        if (!TB) {
            #pragma unroll
            for (int i = 0; i < BPT; i++) {
                int kb = b_r[i], nq = b_c[i];
                Bs[buf][kb][nq*4+0] = tf32r(pb[i].x);
                Bs[buf][kb][nq*4+1] = tf32r(pb[i].y);
                Bs[buf][kb][nq*4+2] = tf32r(pb[i].z);
                Bs[buf][kb][nq*4+3] = tf32r(pb[i].w);
            }
        } else {
            #pragma unroll
            for (int i = 0; i < BPT; i++) {
                int n = b_r[i], kq = b_c[i];
                Bs[buf][kq*4+0][n] = tf32r(pb[i].x);
                Bs[buf][kq*4+1][n] = tf32r(pb[i].y);
                Bs[buf][kq*4+2][n] = tf32r(pb[i].z);
                Bs[buf][kq*4+3][n] = tf32r(pb[i].w);
            }
        }
    };

    auto COMPUTE = [&](int buf) {
        #pragma unroll
        for (int ks = 0; ks < BK/8; ks++) {
            uint32_t af[MT][4];
            uint32_t bf[NT][2];
            #pragma unroll
            for (int mt = 0; mt < MT; mt++) {
                int m0 = wm*WM + mt*16;
                af[mt][0] = __float_as_uint(As[buf][ks*8 + tig    ][m0 + gid    ]);
                af[mt][1] = __float_as_uint(As[buf][ks*8 + tig    ][m0 + gid + 8]);
                af[mt][2] = __float_as_uint(As[buf][ks*8 + tig + 4][m0 + gid    ]);
                af[mt][3] = __float_as_uint(As[buf][ks*8 + tig + 4][m0 + gid + 8]);
            }
            #pragma unroll
            for (int nt = 0; nt < NT; nt++) {
                int n0 = wn*WN + nt*8;
                bf[nt][0] = __float_as_uint(Bs[buf][ks*8 + tig    ][n0 + gid]);
                bf[nt][1] = __float_as_uint(Bs[buf][ks*8 + tig + 4][n0 + gid]);
            }
            #pragma unroll
            for (int mt = 0; mt < MT; mt++)
                #pragma unroll
                for (int nt = 0; nt < NT; nt++)
                    mma_tf32(acc[mt][nt], af[mt], bf[nt]);
        }
    };

    // prologue
    LDG_TILE(0);
    STS_TILE(0);
    __syncthreads();

    int cur = 0;
    for (int k0 = 0; k0 < K; k0 += BK) {
        bool notlast = (k0 + BK < K);
        if (notlast) LDG_TILE(k0 + BK);
        COMPUTE(cur);
        if (notlast) {
            STS_TILE(cur ^ 1);
            __syncthreads();
            cur ^= 1;
        }
    }

    // epilogue
    #pragma unroll
    for (int mt = 0; mt < MT; mt++) {
        #pragma unroll
        for (int nt = 0; nt < NT; nt++) {
            int r = row0 + wm*WM + mt*16 + gid;
            int c = col0 + wn*WN + nt*8 + tig*2;
            float2 v0 = make_float2(acc[mt][nt][0], acc[mt][nt][1]);
            float2 v1 = make_float2(acc[mt][nt][2], acc[mt][nt][3]);
            if (bias) {
                float2 bb = *(const float2*)(bias + c);
                v0.x += bb.x; v0.y += bb.y;
                v1.x += bb.x; v1.y += bb.y;
            }
            float* p0 = C + (size_t)r * ldc + c;
            float* p1 = C + (size_t)(r+8) * ldc + c;
            if (accumulate) {
                float2 c0 = *(const float2*)p0;
                float2 c1 = *(const float2*)p1;
                v0.x += c0.x; v0.y += c0.y;
                v1.x += c1.x; v1.y += c1.y;
            }
            if (relu) {
                v0.x = fmaxf(v0.x, 0.f); v0.y = fmaxf(v0.y, 0.f);
                v1.x = fmaxf(v1.x, 0.f); v1.y = fmaxf(v1.y, 0.f);
            }
            *(float2*)p0 = v0;
            *(float2*)p1 = v1;
        }
    }
}

// ---------------- softmax: warp per row, register resident ----------------
// grid = B*H*T/8 blocks of 256 (8 warps). Reference tril*scale quirk preserved.
__global__ void softmax_kernel(float* __restrict__ S)
{
    int warp = threadIdx.x >> 5;
    int lane = threadIdx.x & 31;
    size_t row = (size_t)blockIdx.x * 8 + warp;
    int t = (int)(row % T_);
    float4* p4 = (float4*)(S + row * T_);

    float4 v[8];
    float m = -1e30f;
    #pragma unroll
    for (int i = 0; i < 8; i++) {
        int idx = i*32 + lane;          // float4 index
        int c   = idx * 4;              // column
        float4 a = p4[idx];
        a.x = (c+0 <= t) ? a.x * SCALE_ : 0.f;
        a.y = (c+1 <= t) ? a.y * SCALE_ : 0.f;
        a.z = (c+2 <= t) ? a.z * SCALE_ : 0.f;
        a.w = (c+3 <= t) ? a.w * SCALE_ : 0.f;
        v[i] = a;
        m = fmaxf(m, fmaxf(fmaxf(a.x, a.y), fmaxf(a.z, a.w)));
    }
    #pragma unroll
    for (int off = 16; off > 0; off >>= 1)
        m = fmaxf(m, __shfl_xor_sync(0xffffffffu, m, off));

    float sum = 0.f;
    #pragma unroll
    for (int i = 0; i < 8; i++) {
        v[i].x = __expf(v[i].x - m);
        v[i].y = __expf(v[i].y - m);
        v[i].z = __expf(v[i].z - m);
        v[i].w = __expf(v[i].w - m);
        sum += v[i].x + v[i].y + v[i].z + v[i].w;
    }
    #pragma unroll
    for (int off = 16; off > 0; off >>= 1)
        sum += __shfl_xor_sync(0xffffffffu, sum, off);

    float inv = 1.0f / sum;
    #pragma unroll
    for (int i = 0; i < 8; i++) {
        v[i].x *= inv; v[i].y *= inv; v[i].z *= inv; v[i].w *= inv;
        p4[i*32 + lane] = v[i];
    }
}

// ---------------- loss: single-pass online logsumexp ----------------
__global__ void lossrow_kernel(const float* __restrict__ logits,
                               const int* __restrict__ tgt,
                               float* __restrict__ rowloss)
{
    __shared__ float2 red[256];
    int row = blockIdx.x;
    int tid = threadIdx.x;
    const float4* p4 = (const float4*)(logits + (size_t)row * V_);

    float m = -1e30f, s = 0.f;
    auto upd = [&](float v) {
        if (v > m) { s = s * __expf(m - v) + 1.0f; m = v; }
        else       { s += __expf(v - m); }
    };
    // V_/4 = 8000 float4s; 31 full strides of 256, then 64-thread tail
    #pragma unroll 4
    for (int j = 0; j < 31; j++) {
        float4 a = p4[tid + j*256];
        upd(a.x); upd(a.y); upd(a.z); upd(a.w);
    }
    if (tid < 64) {
        float4 a = p4[7936 + tid];
        upd(a.x); upd(a.y); upd(a.z); upd(a.w);
    }
    red[tid] = make_float2(m, s);
    __syncthreads();
    for (int off = 128; off > 0; off >>= 1) {
        if (tid < off) {
            float2 a = red[tid], b = red[tid+off];
            float M = fmaxf(a.x, b.x);
            red[tid] = make_float2(M, a.y * __expf(a.x - M) + b.y * __expf(b.x - M));
        }
        __syncthreads();
    }
    if (tid == 0) {
        float lse = red[0].x + logf(red[0].y);
        rowloss[row] = lse - logits[(size_t)row * V_ + tgt[row]];
    }
}

__global__ void lossreduce_kernel(const float* __restrict__ rowloss,
                                  float* __restrict__ out)
{
    __shared__ float red[256];
    int tid = threadIdx.x;
    float s = 0.f;
    for (int i = tid; i < BT_; i += 256) s += rowloss[i];
    red[tid] = s; __syncthreads();
    for (int off = 128; off > 0; off >>= 1) {
        if (tid < off) red[tid] += red[tid+off];
        __syncthreads();
    }
    if (tid == 0) out[0] = red[0] / (float)BT_;
}

// ---------------- host ----------------
static float* sym(const void* s)
{
    void* p = nullptr;
    cudaGetSymbolAddress(&p, s);
    return (float*)p;
}

struct GemmArgs {
    const float *A, *B; float* C; const float* bias;
    int M, N, K, lda, ldb, ldc;
    bool acc, relu;
    int Z, zdiv;
    long long sAd, sAm, sBd, sBm, sCd, sCm;
};

// 128x128 tile, warp grid 2x4, warp tile 64x32
static void gemm128x128(const GemmArgs& g, bool tb)
{
    dim3 grid(g.N / 128, g.M / 128, g.Z);
    if (!tb)
        tgemm_kernel<128,128,16,64,32,0><<<grid, 256>>>(
            g.A, g.B, g.C, g.bias, g.K, g.lda, g.ldb, g.ldc,
            g.acc, g.relu, g.zdiv, g.sAd, g.sAm, g.sBd, g.sBm, g.sCd, g.sCm);
    else
        tgemm_kernel<128,128,16,64,32,1><<<grid, 256>>>(
            g.A, g.B, g.C, g.bias, g.K, g.lda, g.ldb, g.ldc,
            g.acc, g.relu, g.zdiv, g.sAd, g.sAm, g.sBd, g.sBm, g.sCd, g.sCm);
}

// 128x64 tile, warp grid 4x2, warp tile 32x32
static void gemm128x64(const GemmArgs& g)
{
    dim3 grid(g.N / 64, g.M / 128, g.Z);
    tgemm_kernel<128,64,16,32,32,0><<<grid, 256>>>(
        g.A, g.B, g.C, g.bias, g.K, g.lda, g.ldb, g.ldc,
        g.acc, g.relu, g.zdiv, g.sAd, g.sAm, g.sBd, g.sBm, g.sCd, g.sCm);
}

extern "C" void kernel_launch(void* const* d_in, const int* in_sizes, int n_in,
                              void* d_out, int out_size)
{
    const int*   token_ids = (const int*)d_in[0];
    const int*   targets   = (const int*)d_in[1];
    const float* tok_table = (const float*)d_in[2];
    const float* pos_table = (const float*)d_in[3];
    const float* ln1_g = (const float*)d_in[4];
    const float* ln1_b = (const float*)d_in[5];
    const float* Wq = (const float*)d_in[6];
    const float* Wk = (const float*)d_in[7];
    const float* Wv = (const float*)d_in[8];
    const float* Wo = (const float*)d_in[9];
    const float* ln2_g = (const float*)d_in[10];
    const float* ln2_b = (const float*)d_in[11];
    const float* W1 = (const float*)d_in[12];
    const float* b1 = (const float*)d_in[13];
    const float* W2 = (const float*)d_in[14];
    const float* b2 = (const float*)d_in[15];
    const float* lnf_g = (const float*)d_in[16];
    const float* lnf_b = (const float*)d_in[17];
    const float* Wlm = (const float*)d_in[18];
    const float* blm = (const float*)d_in[19];

    float* x    = sym(g_x);
    float* h    = sym(g_h);
    float* qkv  = sym(g_qkv);
    float* wp   = sym(g_wpack);
    float* s    = sym(g_s);
    float* av   = sym(g_av);
    float* ffn  = sym(g_ffn);
    float* rl   = sym(g_rowloss);

    const long long NLOGITS = (long long)BT_ * V_;
    float* out = (float*)d_out;
    bool out_has_logits = ((long long)out_size >= NLOGITS);
    float* logits = out_has_logits ? out : sym(g_logits);

    // embed + weight pack
    embed_kernel<<<(BT_*D_ + 255)/256, 256>>>(token_ids, tok_table, pos_table, x);
    {
        int total = L_ * D_ * QKVW_;
        pack_qkv_kernel<<<(total + 255)/256, 256>>>(Wq, Wk, Wv, wp);
    }

    for (int l = 0; l < L_; l++) {
        ln_kernel<<<BT_, 128>>>(x, ln1_g + l*D_, ln1_b + l*D_, h);

        // fused QKV: [BT,384] @ [384,1152] -> qkv [BT,1152]
        {
            GemmArgs g{h, wp + (long long)l*D_*QKVW_, qkv, nullptr,
                       BT_, QKVW_, D_, D_, QKVW_, QKVW_,
                       false, false, 1, 1, 0,0,0,0,0,0};
            gemm128x128(g, false);
        }

        // scores = q @ k^T (z = b*H + h)
        {
            GemmArgs g{qkv, qkv + H_*HS_, s, nullptr,
                       T_, T_, HS_, QKVW_, QKVW_, T_,
                       false, false, B_*H_, H_,
                       (long long)T_*QKVW_, HS_,
                       (long long)T_*QKVW_, HS_,
                       (long long)H_*T_*T_, (long long)T_*T_};
            gemm128x128(g, true);
        }

        softmax_kernel<<<B_*H_*T_/8, 256>>>(s);

        // av = attn @ v  -> [B,T,H*HS]
        {
            GemmArgs g{s, qkv + 2*H_*HS_, av, nullptr,
                       T_, HS_, T_, T_, QKVW_, D_,
                       false, false, B_*H_, H_,
                       (long long)H_*T_*T_, (long long)T_*T_,
                       (long long)T_*QKVW_, HS_,
                       (long long)T_*D_, HS_};
            gemm128x64(g);
        }

        // x += av @ Wo[l]
        {
            GemmArgs g{av, Wo + (long long)l*H_*HS_*D_, x, nullptr,
                       BT_, D_, H_*HS_, H_*HS_, D_, D_,
                       true, false, 1, 1, 0,0,0,0,0,0};
            gemm128x128(g, false);
        }

        ln_kernel<<<BT_, 128>>>(x, ln2_g + l*D_, ln2_b + l*D_, h);

        // ffn
        {
            GemmArgs g{h, W1 + (long long)l*D_*DFF_, ffn, b1 + l*DFF_,
                       BT_, DFF_, D_, D_, DFF_, DFF_,
                       false, true, 1, 1, 0,0,0,0,0,0};
            gemm128x128(g, false);
        }
        {
            GemmArgs g{ffn, W2 + (long long)l*DFF_*D_, x, b2 + l*D_,
                       BT_, D_, DFF_, DFF_, D_, D_,
                       true, false, 1, 1, 0,0,0,0,0,0};
            gemm128x128(g, false);
        }
    }

    ln_kernel<<<BT_, 128>>>(x, lnf_g, lnf_b, h);

    // LM head
    {
        GemmArgs g{h, Wlm, logits, blm,
                   BT_, V_, D_, D_, V_, V_,
                   false, false, 1, 1, 0,0,0,0,0,0};
        gemm128x128(g, false);
    }

    lossrow_kernel<<<BT_, 256>>>(logits, targets, rl);
    if (out_has_logits && (long long)out_size > NLOGITS) {
        lossreduce_kernel<<<1, 256>>>(rl, out + NLOGITS);
    } else if (!out_has_logits && out_size >= 1) {
        lossreduce_kernel<<<1, 256>>>(rl, out);
    }
}

// round 6
// speedup vs baseline: 2.8042x; 1.1619x over previous
#include <cuda_runtime.h>
#include <cuda_bf16.h>
#include <math.h>
#include <stdint.h>

// Problem dims
#define B_  4
#define T_  1024
#define V_  32000
#define D_  384
#define H_  6
#define HS_ 64
#define L_  6
#define DFF_ 1536
#define BT_ (B_*T_)
#define QKVW_ (3*H_*HS_)   // 1152
#define EPS_ 1e-5f
#define SCALE_ 0.125f

// ---------------- static scratch ----------------
__device__ float g_x[BT_*D_];
__device__ float g_h[BT_*D_];
__device__ float g_qkv[(size_t)BT_*QKVW_];
__device__ float g_wpack[(size_t)L_*QKVW_*D_];   // [L][1152][384] K-major
__device__ float g_woT[(size_t)L_*D_*(H_*HS_)];  // [L][384][384]
__device__ float g_w1T[(size_t)L_*DFF_*D_];      // [L][1536][384]
__device__ float g_w2T[(size_t)L_*D_*DFF_];      // [L][384][1536]
__device__ float g_wlmT[(size_t)V_*D_];          // [32000][384]
__device__ float g_vT[(size_t)D_*BT_];           // [384][4096]
__device__ float g_s[(size_t)B_*H_*T_*T_];
__device__ float g_av[BT_*D_];
__device__ float g_ffn[BT_*DFF_];
__device__ float g_rowloss[BT_];
__device__ float g_logits[(size_t)BT_*V_];

// ---------------- embed ----------------
__global__ void embed_kernel(const int* __restrict__ tok,
                             const float* __restrict__ tt,
                             const float* __restrict__ pt,
                             float* __restrict__ x)
{
    int idx = blockIdx.x * blockDim.x + threadIdx.x;
    if (idx >= BT_*D_) return;
    int bt = idx / D_;
    int d  = idx - bt * D_;
    int t  = bt % T_;
    x[idx] = tt[(size_t)tok[bt] * D_ + d] + pt[t * D_ + d];
}

// ---------------- tiled transpose: out[z][c][r] = in[z][r][c] ----------------
// grid (C/32, R/32, Z), block (32, 8)
__global__ void transpose_kernel(const float* __restrict__ in,
                                 float* __restrict__ out,
                                 int ldi, int ldo, int zdiv,
                                 long long sId, long long sIm,
                                 long long sOd, long long sOm)
{
    __shared__ float tile[32][33];
    int z  = blockIdx.z;
    int zq = z / zdiv;
    int zr = z - zq * zdiv;
    in  += zq * sId + (long long)zr * sIm;
    out += zq * sOd + (long long)zr * sOm;

    int r0 = blockIdx.y * 32;
    int c0 = blockIdx.x * 32;
    int tx = threadIdx.x, ty = threadIdx.y;
    #pragma unroll
    for (int j = 0; j < 4; j++)
        tile[ty + 8*j][tx] = in[(size_t)(r0 + ty + 8*j) * ldi + c0 + tx];
    __syncthreads();
    #pragma unroll
    for (int j = 0; j < 4; j++)
        out[(size_t)(c0 + ty + 8*j) * ldo + r0 + tx] = tile[tx][ty + 8*j];
}

// ---------------- layernorm ----------------
__global__ void ln_kernel(const float* __restrict__ x,
                          const float* __restrict__ g,
                          const float* __restrict__ b,
                          float* __restrict__ y)
{
    __shared__ float rs[128], rq[128];
    int row = blockIdx.x;
    int tid = threadIdx.x;
    const float* xr = x + (size_t)row * D_;
    float s = 0.f, q = 0.f;
    #pragma unroll
    for (int i = tid; i < D_; i += 128) { float v = xr[i]; s += v; q += v*v; }
    rs[tid] = s; rq[tid] = q;
    __syncthreads();
    for (int off = 64; off > 0; off >>= 1) {
        if (tid < off) { rs[tid] += rs[tid+off]; rq[tid] += rq[tid+off]; }
        __syncthreads();
    }
    float mean = rs[0] / D_;
    float var  = rq[0] / D_ - mean * mean;
    float inv  = rsqrtf(var + EPS_);
    float* yr = y + (size_t)row * D_;
    #pragma unroll
    for (int i = tid; i < D_; i += 128)
        yr[i] = (xr[i] - mean) * inv * g[i] + b[i];
}

// ---------------- tf32 helpers ----------------
__device__ __forceinline__ float tf32r(float x)
{
    asm("cvt.rna.tf32.f32 %0, %0;" : "+f"(x));
    return x;
}
#define FU(x) __float_as_uint(x)

__device__ __forceinline__ void mma_tf32(float c[4],
    uint32_t a0, uint32_t a1, uint32_t a2, uint32_t a3,
    uint32_t b0, uint32_t b1)
{
    asm volatile(
        "mma.sync.aligned.m16n8k8.row.col.f32.tf32.tf32.f32 "
        "{%0,%1,%2,%3}, {%4,%5,%6,%7}, {%8,%9}, {%0,%1,%2,%3};"
        : "+f"(c[0]), "+f"(c[1]), "+f"(c[2]), "+f"(c[3])
        : "r"(a0), "r"(a1), "r"(a2), "r"(a3), "r"(b0), "r"(b1));
}

// ---------------- NT tensor-core GEMM, K-major both operands ----------------
// C[M,N] = A[M,K] * B[N,K]^T (+bias)(+C)(relu).
// SMEM natural row-major [row][k] (row = 64B); fragments via LDS.128 with
// k-remap: thread tig supplies k in {4tig..4tig+3} consistently for A and B.
// z-batching: zq=z/zdiv, zr=z%zdiv; ptr += zq*s?d + zr*s?m.
template<int BM, int BN, int WM, int WN>
__global__ void __launch_bounds__(256, 2)
ntgemm_kernel(const float* __restrict__ A,
              const float* __restrict__ B,
              float* __restrict__ C,
              const float* __restrict__ bias,
              int K, int lda, int ldb, int ldc,
              int accumulate, int relu, int zdiv,
              long long sAd, long long sAm,
              long long sBd, long long sBm,
              long long sCd, long long sCm)
{
    constexpr int BK = 16;
    constexpr int MT = WM / 16;
    constexpr int NT = WN / 8;
    constexpr int WARPS_N = BN / WN;
    static_assert((BM/WM) * (BN/WN) == 8, "8 warps");
    constexpr int APT = BM / 64;   // float4s per thread for A tile
    constexpr int BPT = BN / 64;

    __shared__ float As[2][BM][BK];
    __shared__ float Bs[2][BN][BK];

    int z  = blockIdx.z;
    int zq = z / zdiv;
    int zr = z - zq * zdiv;
    A += zq * sAd + (long long)zr * sAm;
    B += zq * sBd + (long long)zr * sBm;
    C += zq * sCd + (long long)zr * sCm;

    const int tid  = threadIdx.x;
    const int lane = tid & 31;
    const int wid  = tid >> 5;
    const int wm   = wid / WARPS_N;
    const int wn   = wid % WARPS_N;
    const int gid  = lane >> 2;
    const int tig4 = (lane & 3) * 4;

    const int row0 = blockIdx.y * BM;
    const int col0 = blockIdx.x * BN;

    float acc[MT][NT][4] = {};

    // staging coordinates: idx4 -> (row, kq)
    const int s_row = tid >> 2;
    const int s_kq  = (tid & 3) * 4;

    float4 pa[APT], pb[BPT];

    auto LDG_TILE = [&](int k0) {
        #pragma unroll
        for (int i = 0; i < APT; i++)
            pa[i] = *(const float4*)(A + (size_t)(row0 + s_row + i*64) * lda + k0 + s_kq);
        #pragma unroll
        for (int i = 0; i < BPT; i++)
            pb[i] = *(const float4*)(B + (size_t)(col0 + s_row + i*64) * ldb + k0 + s_kq);
    };

    auto STS_TILE = [&](int buf) {
        #pragma unroll
        for (int i = 0; i < APT; i++) {
            float4 v = make_float4(tf32r(pa[i].x), tf32r(pa[i].y), tf32r(pa[i].z), tf32r(pa[i].w));
            *(float4*)&As[buf][s_row + i*64][s_kq] = v;
        }
        #pragma unroll
        for (int i = 0; i < BPT; i++) {
            float4 v = make_float4(tf32r(pb[i].x), tf32r(pb[i].y), tf32r(pb[i].z), tf32r(pb[i].w));
            *(float4*)&Bs[buf][s_row + i*64][s_kq] = v;
        }
    };

    auto COMPUTE = [&](int buf) {
        float4 bq[NT];
        #pragma unroll
        for (int nt = 0; nt < NT; nt++)
            bq[nt] = *(const float4*)&Bs[buf][wn*WN + nt*8 + gid][tig4];
        #pragma unroll
        for (int mt = 0; mt < MT; mt++) {
            int m0 = wm*WM + mt*16 + gid;
            float4 a0 = *(const float4*)&As[buf][m0    ][tig4];
            float4 a1 = *(const float4*)&As[buf][m0 + 8][tig4];
            #pragma unroll
            for (int nt = 0; nt < NT; nt++) {
                mma_tf32(acc[mt][nt], FU(a0.x), FU(a1.x), FU(a0.y), FU(a1.y),
                         FU(bq[nt].x), FU(bq[nt].y));
                mma_tf32(acc[mt][nt], FU(a0.z), FU(a1.z), FU(a0.w), FU(a1.w),
                         FU(bq[nt].z), FU(bq[nt].w));
            }
        }
    };

    LDG_TILE(0);
    STS_TILE(0);
    __syncthreads();

    int cur = 0;
    for (int k0 = 0; k0 < K; k0 += BK) {
        bool notlast = (k0 + BK < K);
        if (notlast) LDG_TILE(k0 + BK);
        COMPUTE(cur);
        if (notlast) {
            STS_TILE(cur ^ 1);
            __syncthreads();
            cur ^= 1;
        }
    }

    // epilogue: thread owns (r,c),(r,c+1),(r+8,c),(r+8,c+1)
    #pragma unroll
    for (int mt = 0; mt < MT; mt++) {
        #pragma unroll
        for (int nt = 0; nt < NT; nt++) {
            int r = row0 + wm*WM + mt*16 + gid;
            int c = col0 + wn*WN + nt*8 + (lane & 3)*2;
            float2 v0 = make_float2(acc[mt][nt][0], acc[mt][nt][1]);
            float2 v1 = make_float2(acc[mt][nt][2], acc[mt][nt][3]);
            if (bias) {
                float2 bb = *(const float2*)(bias + c);
                v0.x += bb.x; v0.y += bb.y;
                v1.x += bb.x; v1.y += bb.y;
            }
            float* p0 = C + (size_t)r * ldc + c;
            float* p1 = C + (size_t)(r+8) * ldc + c;
            if (accumulate) {
                float2 c0 = *(const float2*)p0;
                float2 c1 = *(const float2*)p1;
                v0.x += c0.x; v0.y += c0.y;
                v1.x += c1.x; v1.y += c1.y;
            }
            if (relu) {
                v0.x = fmaxf(v0.x, 0.f); v0.y = fmaxf(v0.y, 0.f);
                v1.x = fmaxf(v1.x, 0.f); v1.y = fmaxf(v1.y, 0.f);
            }
            *(float2*)p0 = v0;
            *(float2*)p1 = v1;
        }
    }
}

// ---------------- softmax: warp per row (reference tril*scale quirk) ----------------
__global__ void softmax_kernel(float* __restrict__ S)
{
    int warp = threadIdx.x >> 5;
    int lane = threadIdx.x & 31;
    size_t row = (size_t)blockIdx.x * 8 + warp;
    int t = (int)(row % T_);
    float4* p4 = (float4*)(S + row * T_);

    float4 v[8];
    float m = -1e30f;
    #pragma unroll
    for (int i = 0; i < 8; i++) {
        int idx = i*32 + lane;
        int c   = idx * 4;
        float4 a = p4[idx];
        a.x = (c+0 <= t) ? a.x * SCALE_ : 0.f;
        a.y = (c+1 <= t) ? a.y * SCALE_ : 0.f;
        a.z = (c+2 <= t) ? a.z * SCALE_ : 0.f;
        a.w = (c+3 <= t) ? a.w * SCALE_ : 0.f;
        v[i] = a;
        m = fmaxf(m, fmaxf(fmaxf(a.x, a.y), fmaxf(a.z, a.w)));
    }
    #pragma unroll
    for (int off = 16; off > 0; off >>= 1)
        m = fmaxf(m, __shfl_xor_sync(0xffffffffu, m, off));

    float sum = 0.f;
    #pragma unroll
    for (int i = 0; i < 8; i++) {
        v[i].x = __expf(v[i].x - m);
        v[i].y = __expf(v[i].y - m);
        v[i].z = __expf(v[i].z - m);
        v[i].w = __expf(v[i].w - m);
        sum += v[i].x + v[i].y + v[i].z + v[i].w;
    }
    #pragma unroll
    for (int off = 16; off > 0; off >>= 1)
        sum += __shfl_xor_sync(0xffffffffu, sum, off);

    float inv = 1.0f / sum;
    #pragma unroll
    for (int i = 0; i < 8; i++) {
        v[i].x *= inv; v[i].y *= inv; v[i].z *= inv; v[i].w *= inv;
        p4[i*32 + lane] = v[i];
    }
}

// ---------------- loss: single-pass online logsumexp ----------------
__global__ void lossrow_kernel(const float* __restrict__ logits,
                               const int* __restrict__ tgt,
                               float* __restrict__ rowloss)
{
    __shared__ float2 red[256];
    int row = blockIdx.x;
    int tid = threadIdx.x;
    const float4* p4 = (const float4*)(logits + (size_t)row * V_);

    float m = -1e30f, s = 0.f;
    auto upd = [&](float v) {
        if (v > m) { s = s * __expf(m - v) + 1.0f; m = v; }
        else       { s += __expf(v - m); }
    };
    #pragma unroll 4
    for (int j = 0; j < 31; j++) {
        float4 a = p4[tid + j*256];
        upd(a.x); upd(a.y); upd(a.z); upd(a.w);
    }
    if (tid < 64) {
        float4 a = p4[7936 + tid];
        upd(a.x); upd(a.y); upd(a.z); upd(a.w);
    }
    red[tid] = make_float2(m, s);
    __syncthreads();
    for (int off = 128; off > 0; off >>= 1) {
        if (tid < off) {
            float2 a = red[tid], b = red[tid+off];
            float M = fmaxf(a.x, b.x);
            red[tid] = make_float2(M, a.y * __expf(a.x - M) + b.y * __expf(b.x - M));
        }
        __syncthreads();
    }
    if (tid == 0) {
        float lse = red[0].x + logf(red[0].y);
        rowloss[row] = lse - logits[(size_t)row * V_ + tgt[row]];
    }
}

__global__ void lossreduce_kernel(const float* __restrict__ rowloss,
                                  float* __restrict__ out)
{
    __shared__ float red[256];
    int tid = threadIdx.x;
    float s = 0.f;
    for (int i = tid; i < BT_; i += 256) s += rowloss[i];
    red[tid] = s; __syncthreads();
    for (int off = 128; off > 0; off >>= 1) {
        if (tid < off) red[tid] += red[tid+off];
        __syncthreads();
    }
    if (tid == 0) out[0] = red[0] / (float)BT_;
}

// ---------------- host ----------------
static float* sym(const void* s)
{
    void* p = nullptr;
    cudaGetSymbolAddress(&p, s);
    return (float*)p;
}

struct GemmArgs {
    const float *A, *B; float* C; const float* bias;
    int M, N, K, lda, ldb, ldc;
    bool acc, relu;
    int Z, zdiv;
    long long sAd, sAm, sBd, sBm, sCd, sCm;
};

static void gemm128x128(const GemmArgs& g)
{
    dim3 grid(g.N / 128, g.M / 128, g.Z);
    ntgemm_kernel<128,128,64,32><<<grid, 256>>>(
        g.A, g.B, g.C, g.bias, g.K, g.lda, g.ldb, g.ldc,
        g.acc, g.relu, g.zdiv, g.sAd, g.sAm, g.sBd, g.sBm, g.sCd, g.sCm);
}

static void gemm128x64(const GemmArgs& g)
{
    dim3 grid(g.N / 64, g.M / 128, g.Z);
    ntgemm_kernel<128,64,32,32><<<grid, 256>>>(
        g.A, g.B, g.C, g.bias, g.K, g.lda, g.ldb, g.ldc,
        g.acc, g.relu, g.zdiv, g.sAd, g.sAm, g.sBd, g.sBm, g.sCd, g.sCm);
}

// transpose helper: out[z][c][r] = in[z][r][c], R x C per z
static void transpose(const float* in, float* out, int R, int C,
                      int ldi, int ldo, int Z, int zdiv,
                      long long sId, long long sIm,
                      long long sOd, long long sOm)
{
    dim3 grid(C / 32, R / 32, Z);
    transpose_kernel<<<grid, dim3(32, 8)>>>(in, out, ldi, ldo, zdiv,
                                            sId, sIm, sOd, sOm);
}

extern "C" void kernel_launch(void* const* d_in, const int* in_sizes, int n_in,
                              void* d_out, int out_size)
{
    const int*   token_ids = (const int*)d_in[0];
    const int*   targets   = (const int*)d_in[1];
    const float* tok_table = (const float*)d_in[2];
    const float* pos_table = (const float*)d_in[3];
    const float* ln1_g = (const float*)d_in[4];
    const float* ln1_b = (const float*)d_in[5];
    const float* Wq = (const float*)d_in[6];
    const float* Wk = (const float*)d_in[7];
    const float* Wv = (const float*)d_in[8];
    const float* Wo = (const float*)d_in[9];
    const float* ln2_g = (const float*)d_in[10];
    const float* ln2_b = (const float*)d_in[11];
    const float* W1 = (const float*)d_in[12];
    const float* b1 = (const float*)d_in[13];
    const float* W2 = (const float*)d_in[14];
    const float* b2 = (const float*)d_in[15];
    const float* lnf_g = (const float*)d_in[16];
    const float* lnf_b = (const float*)d_in[17];
    const float* Wlm = (const float*)d_in[18];
    const float* blm = (const float*)d_in[19];

    float* x    = sym(g_x);
    float* h    = sym(g_h);
    float* qkv  = sym(g_qkv);
    float* wp   = sym(g_wpack);
    float* woT  = sym(g_woT);
    float* w1T  = sym(g_w1T);
    float* w2T  = sym(g_w2T);
    float* wlmT = sym(g_wlmT);
    float* vT   = sym(g_vT);
    float* s    = sym(g_s);
    float* av   = sym(g_av);
    float* ffn  = sym(g_ffn);
    float* rl   = sym(g_rowloss);

    const long long NLOGITS = (long long)BT_ * V_;
    float* out = (float*)d_out;
    bool out_has_logits = ((long long)out_size >= NLOGITS);
    float* logits = out_has_logits ? out : sym(g_logits);

    // ---- embed ----
    embed_kernel<<<(BT_*D_ + 255)/256, 256>>>(token_ids, tok_table, pos_table, x);

    // ---- weight packs (transpose to [N][K] K-major) ----
    // Wq/Wk/Wv: per z=(l,h), in [D][HS] -> out rows grp*384 + h*64 + e
    for (int grp = 0; grp < 3; grp++) {
        const float* W = (grp == 0) ? Wq : (grp == 1) ? Wk : Wv;
        transpose(W, wp + (long long)grp*H_*HS_*D_, D_, HS_, HS_, D_,
                  L_*H_, H_,
                  (long long)H_*D_*HS_, (long long)D_*HS_,
                  (long long)QKVW_*D_, (long long)HS_*D_);
    }
    // Wo: per l (zq=l, zr=0 since zdiv=1 => per-l stride goes in sId/sOd!)
    transpose(Wo, woT, H_*HS_, D_, D_, H_*HS_, L_, 1,
              (long long)H_*HS_*D_, 0, (long long)D_*H_*HS_, 0);
    // W1: per l, [D][DFF] -> [DFF][D]
    transpose(W1, w1T, D_, DFF_, DFF_, D_, L_, 1,
              (long long)D_*DFF_, 0, (long long)DFF_*D_, 0);
    // W2: per l, [DFF][D] -> [D][DFF]
    transpose(W2, w2T, DFF_, D_, D_, DFF_, L_, 1,
              (long long)DFF_*D_, 0, (long long)D_*DFF_, 0);
    // Wlm: [D][V] -> [V][D]
    transpose(Wlm, wlmT, D_, V_, V_, D_, 1, 1, 0, 0, 0, 0);

    for (int l = 0; l < L_; l++) {
        ln_kernel<<<BT_, 128>>>(x, ln1_g + l*D_, ln1_b + l*D_, h);

        // fused QKV: [4096,384] x [1152,384]^T -> qkv [4096,1152]
        {
            GemmArgs g{h, wp + (long long)l*QKVW_*D_, qkv, nullptr,
                       BT_, QKVW_, D_, D_, D_, QKVW_,
                       false, false, 1, 1, 0,0,0,0,0,0};
            gemm128x128(g);
        }

        // V^T: qkv cols [768,1152) : [4096 x 384] -> vT [384 x 4096]
        transpose(qkv + 2*H_*HS_, vT, BT_, D_, QKVW_, BT_, 1, 1, 0, 0, 0, 0);

        // scores = q @ k^T : z = b*H + h ; both operands K-major (K=HS)
        {
            GemmArgs g{qkv, qkv + H_*HS_, s, nullptr,
                       T_, T_, HS_, QKVW_, QKVW_, T_,
                       false, false, B_*H_, H_,
                       (long long)T_*QKVW_, HS_,
                       (long long)T_*QKVW_, HS_,
                       (long long)H_*T_*T_, (long long)T_*T_};
            gemm128x128(g);
        }

        softmax_kernel<<<B_*H_*T_/8, 256>>>(s);

        // av = attn @ v : B = vT [e][b*T+t], K = T
        {
            GemmArgs g{s, vT, av, nullptr,
                       T_, HS_, T_, T_, BT_, D_,
                       false, false, B_*H_, H_,
                       (long long)H_*T_*T_, (long long)T_*T_,
                       (long long)T_, (long long)HS_*BT_,
                       (long long)T_*D_, HS_};
            gemm128x64(g);
        }

        // x += av @ Wo[l] : B = woT [d][he]
        {
            GemmArgs g{av, woT + (long long)l*D_*H_*HS_, x, nullptr,
                       BT_, D_, H_*HS_, H_*HS_, H_*HS_, D_,
                       true, false, 1, 1, 0,0,0,0,0,0};
            gemm128x128(g);
        }

        ln_kernel<<<BT_, 128>>>(x, ln2_g + l*D_, ln2_b + l*D_, h);

        // ffn
        {
            GemmArgs g{h, w1T + (long long)l*DFF_*D_, ffn, b1 + l*DFF_,
                       BT_, DFF_, D_, D_, D_, DFF_,
                       false, true, 1, 1, 0,0,0,0,0,0};
            gemm128x128(g);
        }
        {
            GemmArgs g{ffn, w2T + (long long)l*D_*DFF_, x, b2 + l*D_,
                       BT_, D_, DFF_, DFF_, DFF_, D_,
                       true, false, 1, 1, 0,0,0,0,0,0};
            gemm128x128(g);
        }
    }

    ln_kernel<<<BT_, 128>>>(x, lnf_g, lnf_b, h);

    // LM head: B = wlmT [v][d]
    {
        GemmArgs g{h, wlmT, logits, blm,
                   BT_, V_, D_, D_, D_, V_,
                   false, false, 1, 1, 0,0,0,0,0,0};
        gemm128x128(g);
    }

    lossrow_kernel<<<BT_, 256>>>(logits, targets, rl);
    if (out_has_logits && (long long)out_size > NLOGITS) {
        lossreduce_kernel<<<1, 256>>>(rl, out + NLOGITS);
    } else if (!out_has_logits && out_size >= 1) {
        lossreduce_kernel<<<1, 256>>>(rl, out);
    }
}

// round 7
// speedup vs baseline: 3.3823x; 1.2062x over previous
#include <cuda_runtime.h>
#include <cuda_bf16.h>
#include <math.h>
#include <stdint.h>

// Problem dims
#define B_  4
#define T_  1024
#define V_  32000
#define D_  384
#define H_  6
#define HS_ 64
#define L_  6
#define DFF_ 1536
#define BT_ (B_*T_)
#define QKVW_ (3*H_*HS_)   // 1152
#define EPS_ 1e-5f
#define SCALE_ 0.125f

// ---------------- static scratch ----------------
__device__ float g_x[BT_*D_];
__device__ float g_h[BT_*D_];
__device__ float g_qkv[(size_t)BT_*QKVW_];
__device__ float g_wpack[(size_t)L_*QKVW_*D_];   // [L][1152][384] K-major
__device__ float g_woT[(size_t)L_*D_*(H_*HS_)];  // [L][384][384]
__device__ float g_w1T[(size_t)L_*DFF_*D_];      // [L][1536][384]
__device__ float g_w2T[(size_t)L_*D_*DFF_];      // [L][384][1536]
__device__ float g_wlmT[(size_t)V_*D_];          // [32000][384]
__device__ float g_vT[(size_t)D_*BT_];           // [384][4096]
__device__ float g_s[(size_t)B_*H_*T_*T_];
__device__ float g_av[BT_*D_];
__device__ float g_ffn[BT_*DFF_];
__device__ float g_rowloss[BT_];
__device__ float g_logits[(size_t)BT_*V_];

// ---------------- tf32 helper ----------------
__device__ __forceinline__ float tf32r(float x)
{
    asm("cvt.rna.tf32.f32 %0, %0;" : "+f"(x));
    return x;
}
#define FU(x) __float_as_uint(x)

// ---------------- embed ----------------
__global__ void embed_kernel(const int* __restrict__ tok,
                             const float* __restrict__ tt,
                             const float* __restrict__ pt,
                             float* __restrict__ x)
{
    int idx = blockIdx.x * blockDim.x + threadIdx.x;
    if (idx >= BT_*D_) return;
    int bt = idx / D_;
    int d  = idx - bt * D_;
    int t  = bt % T_;
    x[idx] = tt[(size_t)tok[bt] * D_ + d] + pt[t * D_ + d];
}

// ---------------- tiled transpose: out[z][c][r] = in[z][r][c] ----------------
__global__ void transpose_kernel(const float* __restrict__ in,
                                 float* __restrict__ out,
                                 int ldi, int ldo, int zdiv, int roundout,
                                 long long sId, long long sIm,
                                 long long sOd, long long sOm)
{
    __shared__ float tile[32][33];
    int z  = blockIdx.z;
    int zq = z / zdiv;
    int zr = z - zq * zdiv;
    in  += zq * sId + (long long)zr * sIm;
    out += zq * sOd + (long long)zr * sOm;

    int r0 = blockIdx.y * 32;
    int c0 = blockIdx.x * 32;
    int tx = threadIdx.x, ty = threadIdx.y;
    #pragma unroll
    for (int j = 0; j < 4; j++)
        tile[ty + 8*j][tx] = in[(size_t)(r0 + ty + 8*j) * ldi + c0 + tx];
    __syncthreads();
    #pragma unroll
    for (int j = 0; j < 4; j++) {
        float v = tile[tx][ty + 8*j];
        if (roundout) v = tf32r(v);
        out[(size_t)(c0 + ty + 8*j) * ldo + r0 + tx] = v;
    }
}

// ---------------- layernorm (output rounded to tf32 — always feeds a GEMM) ----------------
__global__ void ln_kernel(const float* __restrict__ x,
                          const float* __restrict__ g,
                          const float* __restrict__ b,
                          float* __restrict__ y)
{
    __shared__ float rs[128], rq[128];
    int row = blockIdx.x;
    int tid = threadIdx.x;
    const float* xr = x + (size_t)row * D_;
    float s = 0.f, q = 0.f;
    #pragma unroll
    for (int i = tid; i < D_; i += 128) { float v = xr[i]; s += v; q += v*v; }
    rs[tid] = s; rq[tid] = q;
    __syncthreads();
    for (int off = 64; off > 0; off >>= 1) {
        if (tid < off) { rs[tid] += rs[tid+off]; rq[tid] += rq[tid+off]; }
        __syncthreads();
    }
    float mean = rs[0] / D_;
    float var  = rq[0] / D_ - mean * mean;
    float inv  = rsqrtf(var + EPS_);
    float* yr = y + (size_t)row * D_;
    #pragma unroll
    for (int i = tid; i < D_; i += 128)
        yr[i] = tf32r((xr[i] - mean) * inv * g[i] + b[i]);
}

__device__ __forceinline__ void mma_tf32(float c[4],
    uint32_t a0, uint32_t a1, uint32_t a2, uint32_t a3,
    uint32_t b0, uint32_t b1)
{
    asm volatile(
        "mma.sync.aligned.m16n8k8.row.col.f32.tf32.tf32.f32 "
        "{%0,%1,%2,%3}, {%4,%5,%6,%7}, {%8,%9}, {%0,%1,%2,%3};"
        : "+f"(c[0]), "+f"(c[1]), "+f"(c[2]), "+f"(c[3])
        : "r"(a0), "r"(a1), "r"(a2), "r"(a3), "r"(b0), "r"(b1));
}

// ---------------- NT tensor-core GEMM, cp.async 3-stage pipeline ----------------
// C[M,N] = A[M,K] * B[N,K]^T (+bias)(+C)(relu)(round). Operands assumed pre-rounded
// to tf32 by their producers; staged raw via cp.async (no register roundtrip).
template<int BM, int BN, int WM, int WN>
__global__ void __launch_bounds__(256, 2)
ntgemm_kernel(const float* __restrict__ A,
              const float* __restrict__ B,
              float* __restrict__ C,
              const float* __restrict__ bias,
              int K, int lda, int ldb, int ldc,
              int accumulate, int relu, int roundout, int zdiv,
              long long sAd, long long sAm,
              long long sBd, long long sBm,
              long long sCd, long long sCm)
{
    constexpr int BK = 16;
    constexpr int NSTAGE = 3;
    constexpr int MT = WM / 16;
    constexpr int NT = WN / 8;
    constexpr int WARPS_N = BN / WN;
    static_assert((BM/WM) * (BN/WN) == 8, "8 warps");
    constexpr int APT = BM / 64;   // 16B chunks per thread for A tile
    constexpr int BPT = BN / 64;

    __shared__ float As[NSTAGE][BM][BK];
    __shared__ float Bs[NSTAGE][BN][BK];

    int z  = blockIdx.z;
    int zq = z / zdiv;
    int zr = z - zq * zdiv;
    A += zq * sAd + (long long)zr * sAm;
    B += zq * sBd + (long long)zr * sBm;
    C += zq * sCd + (long long)zr * sCm;

    const int tid  = threadIdx.x;
    const int lane = tid & 31;
    const int wid  = tid >> 5;
    const int wm   = wid / WARPS_N;
    const int wn   = wid % WARPS_N;
    const int gid  = lane >> 2;
    const int tig4 = (lane & 3) * 4;

    const int row0 = blockIdx.y * BM;
    const int col0 = blockIdx.x * BN;

    float acc[MT][NT][4] = {};

    const int s_row = tid >> 2;          // 0..63
    const int s_kq  = (tid & 3) * 4;     // k offset (floats)

    auto ISSUE = [&](int stage, int k0) {
        if (k0 < K) {
            #pragma unroll
            for (int i = 0; i < APT; i++) {
                uint32_t dst = (uint32_t)__cvta_generic_to_shared(&As[stage][s_row + i*64][s_kq]);
                const float* src = A + (size_t)(row0 + s_row + i*64) * lda + k0 + s_kq;
                asm volatile("cp.async.cg.shared.global [%0], [%1], 16;\n" :: "r"(dst), "l"(src));
            }
            #pragma unroll
            for (int i = 0; i < BPT; i++) {
                uint32_t dst = (uint32_t)__cvta_generic_to_shared(&Bs[stage][s_row + i*64][s_kq]);
                const float* src = B + (size_t)(col0 + s_row + i*64) * ldb + k0 + s_kq;
                asm volatile("cp.async.cg.shared.global [%0], [%1], 16;\n" :: "r"(dst), "l"(src));
            }
        }
        asm volatile("cp.async.commit_group;\n");
    };

    auto COMPUTE = [&](int buf) {
        float4 bq[NT];
        #pragma unroll
        for (int nt = 0; nt < NT; nt++)
            bq[nt] = *(const float4*)&Bs[buf][wn*WN + nt*8 + gid][tig4];
        #pragma unroll
        for (int mt = 0; mt < MT; mt++) {
            int m0 = wm*WM + mt*16 + gid;
            float4 a0 = *(const float4*)&As[buf][m0    ][tig4];
            float4 a1 = *(const float4*)&As[buf][m0 + 8][tig4];
            #pragma unroll
            for (int nt = 0; nt < NT; nt++) {
                mma_tf32(acc[mt][nt], FU(a0.x), FU(a1.x), FU(a0.y), FU(a1.y),
                         FU(bq[nt].x), FU(bq[nt].y));
                mma_tf32(acc[mt][nt], FU(a0.z), FU(a1.z), FU(a0.w), FU(a1.w),
                         FU(bq[nt].z), FU(bq[nt].w));
            }
        }
    };

    // prologue: stages 0..NSTAGE-2
    ISSUE(0, 0);
    ISSUE(1, BK);

    const int niter = K / BK;
    for (int it = 0; it < niter; it++) {
        asm volatile("cp.async.wait_group 1;\n");
        __syncthreads();
        ISSUE((it + NSTAGE - 1) % NSTAGE, (it + NSTAGE - 1) * BK);
        COMPUTE(it % NSTAGE);
    }

    // epilogue
    #pragma unroll
    for (int mt = 0; mt < MT; mt++) {
        #pragma unroll
        for (int nt = 0; nt < NT; nt++) {
            int r = row0 + wm*WM + mt*16 + gid;
            int c = col0 + wn*WN + nt*8 + (lane & 3)*2;
            float2 v0 = make_float2(acc[mt][nt][0], acc[mt][nt][1]);
            float2 v1 = make_float2(acc[mt][nt][2], acc[mt][nt][3]);
            if (bias) {
                float2 bb = *(const float2*)(bias + c);
                v0.x += bb.x; v0.y += bb.y;
                v1.x += bb.x; v1.y += bb.y;
            }
            float* p0 = C + (size_t)r * ldc + c;
            float* p1 = C + (size_t)(r+8) * ldc + c;
            if (accumulate) {
                float2 c0 = *(const float2*)p0;
                float2 c1 = *(const float2*)p1;
                v0.x += c0.x; v0.y += c0.y;
                v1.x += c1.x; v1.y += c1.y;
            }
            if (relu) {
                v0.x = fmaxf(v0.x, 0.f); v0.y = fmaxf(v0.y, 0.f);
                v1.x = fmaxf(v1.x, 0.f); v1.y = fmaxf(v1.y, 0.f);
            }
            if (roundout) {
                v0.x = tf32r(v0.x); v0.y = tf32r(v0.y);
                v1.x = tf32r(v1.x); v1.y = tf32r(v1.y);
            }
            *(float2*)p0 = v0;
            *(float2*)p1 = v1;
        }
    }
}

// ---------------- softmax: warp per row (tril*scale quirk), tf32-rounded output ----------------
__global__ void softmax_kernel(float* __restrict__ S)
{
    int warp = threadIdx.x >> 5;
    int lane = threadIdx.x & 31;
    size_t row = (size_t)blockIdx.x * 8 + warp;
    int t = (int)(row % T_);
    float4* p4 = (float4*)(S + row * T_);

    float4 v[8];
    float m = -1e30f;
    #pragma unroll
    for (int i = 0; i < 8; i++) {
        int idx = i*32 + lane;
        int c   = idx * 4;
        float4 a = p4[idx];
        a.x = (c+0 <= t) ? a.x * SCALE_ : 0.f;
        a.y = (c+1 <= t) ? a.y * SCALE_ : 0.f;
        a.z = (c+2 <= t) ? a.z * SCALE_ : 0.f;
        a.w = (c+3 <= t) ? a.w * SCALE_ : 0.f;
        v[i] = a;
        m = fmaxf(m, fmaxf(fmaxf(a.x, a.y), fmaxf(a.z, a.w)));
    }
    #pragma unroll
    for (int off = 16; off > 0; off >>= 1)
        m = fmaxf(m, __shfl_xor_sync(0xffffffffu, m, off));

    float sum = 0.f;
    #pragma unroll
    for (int i = 0; i < 8; i++) {
        v[i].x = __expf(v[i].x - m);
        v[i].y = __expf(v[i].y - m);
        v[i].z = __expf(v[i].z - m);
        v[i].w = __expf(v[i].w - m);
        sum += v[i].x + v[i].y + v[i].z + v[i].w;
    }
    #pragma unroll
    for (int off = 16; off > 0; off >>= 1)
        sum += __shfl_xor_sync(0xffffffffu, sum, off);

    float inv = 1.0f / sum;
    #pragma unroll
    for (int i = 0; i < 8; i++) {
        v[i].x = tf32r(v[i].x * inv);
        v[i].y = tf32r(v[i].y * inv);
        v[i].z = tf32r(v[i].z * inv);
        v[i].w = tf32r(v[i].w * inv);
        p4[i*32 + lane] = v[i];
    }
}

// ---------------- loss: single-pass online logsumexp ----------------
__global__ void lossrow_kernel(const float* __restrict__ logits,
                               const int* __restrict__ tgt,
                               float* __restrict__ rowloss)
{
    __shared__ float2 red[256];
    int row = blockIdx.x;
    int tid = threadIdx.x;
    const float4* p4 = (const float4*)(logits + (size_t)row * V_);

    float m = -1e30f, s = 0.f;
    auto upd = [&](float v) {
        if (v > m) { s = s * __expf(m - v) + 1.0f; m = v; }
        else       { s += __expf(v - m); }
    };
    #pragma unroll 4
    for (int j = 0; j < 31; j++) {
        float4 a = p4[tid + j*256];
        upd(a.x); upd(a.y); upd(a.z); upd(a.w);
    }
    if (tid < 64) {
        float4 a = p4[7936 + tid];
        upd(a.x); upd(a.y); upd(a.z); upd(a.w);
    }
    red[tid] = make_float2(m, s);
    __syncthreads();
    for (int off = 128; off > 0; off >>= 1) {
        if (tid < off) {
            float2 a = red[tid], b = red[tid+off];
            float M = fmaxf(a.x, b.x);
            red[tid] = make_float2(M, a.y * __expf(a.x - M) + b.y * __expf(b.x - M));
        }
        __syncthreads();
    }
    if (tid == 0) {
        float lse = red[0].x + logf(red[0].y);
        rowloss[row] = lse - logits[(size_t)row * V_ + tgt[row]];
    }
}

__global__ void lossreduce_kernel(const float* __restrict__ rowloss,
                                  float* __restrict__ out)
{
    __shared__ float red[256];
    int tid = threadIdx.x;
    float s = 0.f;
    for (int i = tid; i < BT_; i += 256) s += rowloss[i];
    red[tid] = s; __syncthreads();
    for (int off = 128; off > 0; off >>= 1) {
        if (tid < off) red[tid] += red[tid+off];
        __syncthreads();
    }
    if (tid == 0) out[0] = red[0] / (float)BT_;
}

// ---------------- host ----------------
static float* sym(const void* s)
{
    void* p = nullptr;
    cudaGetSymbolAddress(&p, s);
    return (float*)p;
}

struct GemmArgs {
    const float *A, *B; float* C; const float* bias;
    int M, N, K, lda, ldb, ldc;
    bool acc, relu, round;
    int Z, zdiv;
    long long sAd, sAm, sBd, sBm, sCd, sCm;
};

static void gemm128x128(const GemmArgs& g)
{
    dim3 grid(g.N / 128, g.M / 128, g.Z);
    ntgemm_kernel<128,128,64,32><<<grid, 256>>>(
        g.A, g.B, g.C, g.bias, g.K, g.lda, g.ldb, g.ldc,
        g.acc, g.relu, g.round, g.zdiv, g.sAd, g.sAm, g.sBd, g.sBm, g.sCd, g.sCm);
}

static void gemm128x64(const GemmArgs& g)
{
    dim3 grid(g.N / 64, g.M / 128, g.Z);
    ntgemm_kernel<128,64,32,32><<<grid, 256>>>(
        g.A, g.B, g.C, g.bias, g.K, g.lda, g.ldb, g.ldc,
        g.acc, g.relu, g.round, g.zdiv, g.sAd, g.sAm, g.sBd, g.sBm, g.sCd, g.sCm);
}

static void transpose(const float* in, float* out, int R, int C,
                      int ldi, int ldo, int Z, int zdiv, int roundout,
                      long long sId, long long sIm,
                      long long sOd, long long sOm)
{
    dim3 grid(C / 32, R / 32, Z);
    transpose_kernel<<<grid, dim3(32, 8)>>>(in, out, ldi, ldo, zdiv, roundout,
                                            sId, sIm, sOd, sOm);
}

extern "C" void kernel_launch(void* const* d_in, const int* in_sizes, int n_in,
                              void* d_out, int out_size)
{
    const int*   token_ids = (const int*)d_in[0];
    const int*   targets   = (const int*)d_in[1];
    const float* tok_table = (const float*)d_in[2];
    const float* pos_table = (const float*)d_in[3];
    const float* ln1_g = (const float*)d_in[4];
    const float* ln1_b = (const float*)d_in[5];
    const float* Wq = (const float*)d_in[6];
    const float* Wk = (const float*)d_in[7];
    const float* Wv = (const float*)d_in[8];
    const float* Wo = (const float*)d_in[9];
    const float* ln2_g = (const float*)d_in[10];
    const float* ln2_b = (const float*)d_in[11];
    const float* W1 = (const float*)d_in[12];
    const float* b1 = (const float*)d_in[13];
    const float* W2 = (const float*)d_in[14];
    const float* b2 = (const float*)d_in[15];
    const float* lnf_g = (const float*)d_in[16];
    const float* lnf_b = (const float*)d_in[17];
    const float* Wlm = (const float*)d_in[18];
    const float* blm = (const float*)d_in[19];

    float* x    = sym(g_x);
    float* h    = sym(g_h);
    float* qkv  = sym(g_qkv);
    float* wp   = sym(g_wpack);
    float* woT  = sym(g_woT);
    float* w1T  = sym(g_w1T);
    float* w2T  = sym(g_w2T);
    float* wlmT = sym(g_wlmT);
    float* vT   = sym(g_vT);
    float* s    = sym(g_s);
    float* av   = sym(g_av);
    float* ffn  = sym(g_ffn);
    float* rl   = sym(g_rowloss);

    const long long NLOGITS = (long long)BT_ * V_;
    float* out = (float*)d_out;
    bool out_has_logits = ((long long)out_size >= NLOGITS);
    float* logits = out_has_logits ? out : sym(g_logits);

    // ---- embed ----
    embed_kernel<<<(BT_*D_ + 255)/256, 256>>>(token_ids, tok_table, pos_table, x);

    // ---- weight packs (transpose to [N][K] K-major, round to tf32) ----
    for (int grp = 0; grp < 3; grp++) {
        const float* W = (grp == 0) ? Wq : (grp == 1) ? Wk : Wv;
        transpose(W, wp + (long long)grp*H_*HS_*D_, D_, HS_, HS_, D_,
                  L_*H_, H_, 1,
                  (long long)H_*D_*HS_, (long long)D_*HS_,
                  (long long)QKVW_*D_, (long long)HS_*D_);
    }
    transpose(Wo, woT, H_*HS_, D_, D_, H_*HS_, L_, 1, 1,
              (long long)H_*HS_*D_, 0, (long long)D_*H_*HS_, 0);
    transpose(W1, w1T, D_, DFF_, DFF_, D_, L_, 1, 1,
              (long long)D_*DFF_, 0, (long long)DFF_*D_, 0);
    transpose(W2, w2T, DFF_, D_, D_, DFF_, L_, 1, 1,
              (long long)DFF_*D_, 0, (long long)D_*DFF_, 0);
    transpose(Wlm, wlmT, D_, V_, V_, D_, 1, 1, 1, 0, 0, 0, 0);

    for (int l = 0; l < L_; l++) {
        ln_kernel<<<BT_, 128>>>(x, ln1_g + l*D_, ln1_b + l*D_, h);

        // fused QKV (output rounded: q,k,v feed GEMMs)
        {
            GemmArgs g{h, wp + (long long)l*QKVW_*D_, qkv, nullptr,
                       BT_, QKVW_, D_, D_, D_, QKVW_,
                       false, false, true, 1, 1, 0,0,0,0,0,0};
            gemm128x128(g);
        }

        // V^T (values already tf32-rounded)
        transpose(qkv + 2*H_*HS_, vT, BT_, D_, QKVW_, BT_, 1, 1, 0, 0, 0, 0, 0);

        // scores = q @ k^T (softmax rounds later)
        {
            GemmArgs g{qkv, qkv + H_*HS_, s, nullptr,
                       T_, T_, HS_, QKVW_, QKVW_, T_,
                       false, false, false, B_*H_, H_,
                       (long long)T_*QKVW_, HS_,
                       (long long)T_*QKVW_, HS_,
                       (long long)H_*T_*T_, (long long)T_*T_};
            gemm128x128(g);
        }

        softmax_kernel<<<B_*H_*T_/8, 256>>>(s);

        // av = attn @ v (round: feeds Wo GEMM)
        {
            GemmArgs g{s, vT, av, nullptr,
                       T_, HS_, T_, T_, BT_, D_,
                       false, false, true, B_*H_, H_,
                       (long long)H_*T_*T_, (long long)T_*T_,
                       (long long)T_, (long long)HS_*BT_,
                       (long long)T_*D_, HS_};
            gemm128x64(g);
        }

        // x += av @ Wo[l] (residual: no rounding)
        {
            GemmArgs g{av, woT + (long long)l*D_*H_*HS_, x, nullptr,
                       BT_, D_, H_*HS_, H_*HS_, H_*HS_, D_,
                       true, false, false, 1, 1, 0,0,0,0,0,0};
            gemm128x128(g);
        }

        ln_kernel<<<BT_, 128>>>(x, ln2_g + l*D_, ln2_b + l*D_, h);

        // ffn1 (relu + round: feeds ffn2)
        {
            GemmArgs g{h, w1T + (long long)l*DFF_*D_, ffn, b1 + l*DFF_,
                       BT_, DFF_, D_, D_, D_, DFF_,
                       false, true, true, 1, 1, 0,0,0,0,0,0};
            gemm128x128(g);
        }
        // ffn2 (residual: no rounding)
        {
            GemmArgs g{ffn, w2T + (long long)l*D_*DFF_, x, b2 + l*D_,
                       BT_, D_, DFF_, DFF_, DFF_, D_,
                       true, false, false, 1, 1, 0,0,0,0,0,0};
            gemm128x128(g);
        }
    }

    ln_kernel<<<BT_, 128>>>(x, lnf_g, lnf_b, h);

    // LM head (logits: exact fp32 accum output, no rounding)
    {
        GemmArgs g{h, wlmT, logits, blm,
                   BT_, V_, D_, D_, D_, V_,
                   false, false, false, 1, 1, 0,0,0,0,0,0};
        gemm128x128(g);
    }

    lossrow_kernel<<<BT_, 256>>>(logits, targets, rl);
    if (out_has_logits && (long long)out_size > NLOGITS) {
        lossreduce_kernel<<<1, 256>>>(rl, out + NLOGITS);
    } else if (!out_has_logits && out_size >= 1) {
        lossreduce_kernel<<<1, 256>>>(rl, out);
    }
}

// round 8
// speedup vs baseline: 3.4584x; 1.0225x over previous
#include <cuda_runtime.h>
#include <cuda_bf16.h>
#include <math.h>
#include <stdint.h>

// Problem dims
#define B_  4
#define T_  1024
#define V_  32000
#define D_  384
#define H_  6
#define HS_ 64
#define L_  6
#define DFF_ 1536
#define BT_ (B_*T_)
#define QKVW_ (3*H_*HS_)   // 1152
#define NCH_ (V_/128)      // 250 LM-head column chunks
#define EPS_ 1e-5f
#define SCALE_ 0.125f

// ---------------- static scratch ----------------
__device__ float g_x[BT_*D_];
__device__ float g_h[BT_*D_];
__device__ float g_qkv[(size_t)BT_*QKVW_];
__device__ float g_wpack[(size_t)L_*QKVW_*D_];
__device__ float g_woT[(size_t)L_*D_*(H_*HS_)];
__device__ float g_w1T[(size_t)L_*DFF_*D_];
__device__ float g_w2T[(size_t)L_*D_*DFF_];
__device__ float g_wlmT[(size_t)V_*D_];
__device__ float g_vT[(size_t)D_*BT_];
__device__ float g_s[(size_t)B_*H_*T_*T_];
__device__ float g_av[BT_*D_];
__device__ float g_ffn[BT_*DFF_];
__device__ float g_wm[B_*H_*T_];                 // masked weight per row
__device__ float g_sufv[(size_t)B_*H_*T_*HS_];   // suffix sums of V
__device__ float2 g_lsepart[(size_t)BT_*NCH_];   // LM-head partial (max,sumexp)
__device__ float g_rowloss[BT_];
__device__ float g_logits[(size_t)BT_*V_];

// ---------------- tf32 helper ----------------
__device__ __forceinline__ float tf32r(float x)
{
    asm("cvt.rna.tf32.f32 %0, %0;" : "+f"(x));
    return x;
}
#define FU(x) __float_as_uint(x)

// ---------------- embed ----------------
__global__ void embed_kernel(const int* __restrict__ tok,
                             const float* __restrict__ tt,
                             const float* __restrict__ pt,
                             float* __restrict__ x)
{
    int idx = blockIdx.x * blockDim.x + threadIdx.x;
    if (idx >= BT_*D_) return;
    int bt = idx / D_;
    int d  = idx - bt * D_;
    int t  = bt % T_;
    x[idx] = tt[(size_t)tok[bt] * D_ + d] + pt[t * D_ + d];
}

// ---------------- tiled transpose ----------------
__global__ void transpose_kernel(const float* __restrict__ in,
                                 float* __restrict__ out,
                                 int ldi, int ldo, int zdiv, int roundout,
                                 long long sId, long long sIm,
                                 long long sOd, long long sOm)
{
    __shared__ float tile[32][33];
    int z  = blockIdx.z;
    int zq = z / zdiv;
    int zr = z - zq * zdiv;
    in  += zq * sId + (long long)zr * sIm;
    out += zq * sOd + (long long)zr * sOm;

    int r0 = blockIdx.y * 32;
    int c0 = blockIdx.x * 32;
    int tx = threadIdx.x, ty = threadIdx.y;
    #pragma unroll
    for (int j = 0; j < 4; j++)
        tile[ty + 8*j][tx] = in[(size_t)(r0 + ty + 8*j) * ldi + c0 + tx];
    __syncthreads();
    #pragma unroll
    for (int j = 0; j < 4; j++) {
        float v = tile[tx][ty + 8*j];
        if (roundout) v = tf32r(v);
        out[(size_t)(c0 + ty + 8*j) * ldo + r0 + tx] = v;
    }
}

// ---------------- layernorm (tf32-rounded output) ----------------
__global__ void ln_kernel(const float* __restrict__ x,
                          const float* __restrict__ g,
                          const float* __restrict__ b,
                          float* __restrict__ y)
{
    __shared__ float rs[128], rq[128];
    int row = blockIdx.x;
    int tid = threadIdx.x;
    const float* xr = x + (size_t)row * D_;
    float s = 0.f, q = 0.f;
    #pragma unroll
    for (int i = tid; i < D_; i += 128) { float v = xr[i]; s += v; q += v*v; }
    rs[tid] = s; rq[tid] = q;
    __syncthreads();
    for (int off = 64; off > 0; off >>= 1) {
        if (tid < off) { rs[tid] += rs[tid+off]; rq[tid] += rq[tid+off]; }
        __syncthreads();
    }
    float mean = rs[0] / D_;
    float var  = rq[0] / D_ - mean * mean;
    float inv  = rsqrtf(var + EPS_);
    float* yr = y + (size_t)row * D_;
    #pragma unroll
    for (int i = tid; i < D_; i += 128)
        yr[i] = tf32r((xr[i] - mean) * inv * g[i] + b[i]);
}

__device__ __forceinline__ void mma_tf32(float c[4],
    uint32_t a0, uint32_t a1, uint32_t a2, uint32_t a3,
    uint32_t b0, uint32_t b1)
{
    asm volatile(
        "mma.sync.aligned.m16n8k8.row.col.f32.tf32.tf32.f32 "
        "{%0,%1,%2,%3}, {%4,%5,%6,%7}, {%8,%9}, {%0,%1,%2,%3};"
        : "+f"(c[0]), "+f"(c[1]), "+f"(c[2]), "+f"(c[3])
        : "r"(a0), "r"(a1), "r"(a2), "r"(a3), "r"(b0), "r"(b1));
}

// ---------------- NT tensor-core GEMM, cp.async 3-stage pipeline ----------------
// causal: 0 none; 1 skip blocks with col0 > row0 (scores); 2 K_eff = row0+BM (AV)
// lsepart: if non-null, epilogue writes per-(row,chunk) (max,sumexp) partials.
template<int BM, int BN, int WM, int WN>
__global__ void __launch_bounds__(256, 2)
ntgemm_kernel(const float* __restrict__ A,
              const float* __restrict__ B,
              float* __restrict__ C,
              const float* __restrict__ bias,
              int K, int lda, int ldb, int ldc,
              int accumulate, int relu, int roundout,
              int causal, float2* lsepart, int zdiv,
              long long sAd, long long sAm,
              long long sBd, long long sBm,
              long long sCd, long long sCm)
{
    constexpr int BK = 16;
    constexpr int NSTAGE = 3;
    constexpr int MT = WM / 16;
    constexpr int NT = WN / 8;
    constexpr int WARPS_N = BN / WN;
    static_assert((BM/WM) * (BN/WN) == 8, "8 warps");
    constexpr int APT = BM / 64;
    constexpr int BPT = BN / 64;

    __shared__ float As[NSTAGE][BM][BK];
    __shared__ float Bs[NSTAGE][BN][BK];

    const int row0 = blockIdx.y * BM;
    const int col0 = blockIdx.x * BN;
    if (causal == 1 && col0 > row0) return;
    if (causal == 2) K = min(K, row0 + BM);

    int z  = blockIdx.z;
    int zq = z / zdiv;
    int zr = z - zq * zdiv;
    A += zq * sAd + (long long)zr * sAm;
    B += zq * sBd + (long long)zr * sBm;
    C += zq * sCd + (long long)zr * sCm;

    const int tid  = threadIdx.x;
    const int lane = tid & 31;
    const int wid  = tid >> 5;
    const int wm   = wid / WARPS_N;
    const int wn   = wid % WARPS_N;
    const int gid  = lane >> 2;
    const int tig4 = (lane & 3) * 4;

    float acc[MT][NT][4] = {};

    const int s_row = tid >> 2;
    const int s_kq  = (tid & 3) * 4;

    auto ISSUE = [&](int stage, int k0) {
        if (k0 < K) {
            #pragma unroll
            for (int i = 0; i < APT; i++) {
                uint32_t dst = (uint32_t)__cvta_generic_to_shared(&As[stage][s_row + i*64][s_kq]);
                const float* src = A + (size_t)(row0 + s_row + i*64) * lda + k0 + s_kq;
                asm volatile("cp.async.cg.shared.global [%0], [%1], 16;\n" :: "r"(dst), "l"(src));
            }
            #pragma unroll
            for (int i = 0; i < BPT; i++) {
                uint32_t dst = (uint32_t)__cvta_generic_to_shared(&Bs[stage][s_row + i*64][s_kq]);
                const float* src = B + (size_t)(col0 + s_row + i*64) * ldb + k0 + s_kq;
                asm volatile("cp.async.cg.shared.global [%0], [%1], 16;\n" :: "r"(dst), "l"(src));
            }
        }
        asm volatile("cp.async.commit_group;\n");
    };

    auto COMPUTE = [&](int buf) {
        float4 bq[NT];
        #pragma unroll
        for (int nt = 0; nt < NT; nt++)
            bq[nt] = *(const float4*)&Bs[buf][wn*WN + nt*8 + gid][tig4];
        #pragma unroll
        for (int mt = 0; mt < MT; mt++) {
            int m0 = wm*WM + mt*16 + gid;
            float4 a0 = *(const float4*)&As[buf][m0    ][tig4];
            float4 a1 = *(const float4*)&As[buf][m0 + 8][tig4];
            #pragma unroll
            for (int nt = 0; nt < NT; nt++) {
                mma_tf32(acc[mt][nt], FU(a0.x), FU(a1.x), FU(a0.y), FU(a1.y),
                         FU(bq[nt].x), FU(bq[nt].y));
                mma_tf32(acc[mt][nt], FU(a0.z), FU(a1.z), FU(a0.w), FU(a1.w),
                         FU(bq[nt].z), FU(bq[nt].w));
            }
        }
    };

    ISSUE(0, 0);
    ISSUE(1, BK);

    const int niter = K / BK;
    for (int it = 0; it < niter; it++) {
        asm volatile("cp.async.wait_group 1;\n");
        __syncthreads();
        ISSUE((it + NSTAGE - 1) % NSTAGE, (it + NSTAGE - 1) * BK);
        COMPUTE(it % NSTAGE);
    }

    if (lsepart) {
        // drain pipeline, then reuse stage-0 SMEM for per-row partials
        asm volatile("cp.async.wait_group 0;\n");
        __syncthreads();
        float2* lse_s = (float2*)&As[0][0][0];   // BM * WARPS_N float2 = 4KB
        #pragma unroll
        for (int mt = 0; mt < MT; mt++) {
            float va[2][NT*2];
            #pragma unroll
            for (int nt = 0; nt < NT; nt++) {
                int r = row0 + wm*WM + mt*16 + gid;
                int c = col0 + wn*WN + nt*8 + (lane & 3)*2;
                float2 v0 = make_float2(acc[mt][nt][0], acc[mt][nt][1]);
                float2 v1 = make_float2(acc[mt][nt][2], acc[mt][nt][3]);
                if (bias) {
                    float2 bb = *(const float2*)(bias + c);
                    v0.x += bb.x; v0.y += bb.y;
                    v1.x += bb.x; v1.y += bb.y;
                }
                *(float2*)(C + (size_t)r * ldc + c)     = v0;
                *(float2*)(C + (size_t)(r+8) * ldc + c) = v1;
                va[0][nt*2] = v0.x; va[0][nt*2+1] = v0.y;
                va[1][nt*2] = v1.x; va[1][nt*2+1] = v1.y;
            }
            #pragma unroll
            for (int hf = 0; hf < 2; hf++) {
                float mx = va[hf][0];
                #pragma unroll
                for (int j = 1; j < NT*2; j++) mx = fmaxf(mx, va[hf][j]);
                float sm = 0.f;
                #pragma unroll
                for (int j = 0; j < NT*2; j++) sm += __expf(va[hf][j] - mx);
                #pragma unroll
                for (int off = 1; off <= 2; off <<= 1) {
                    float mo = __shfl_xor_sync(0xffffffffu, mx, off);
                    float so = __shfl_xor_sync(0xffffffffu, sm, off);
                    float M = fmaxf(mx, mo);
                    sm = sm*__expf(mx - M) + so*__expf(mo - M);
                    mx = M;
                }
                if ((lane & 3) == 0) {
                    int rl = wm*WM + mt*16 + gid + hf*8;
                    lse_s[rl*WARPS_N + wn] = make_float2(mx, sm);
                }
            }
        }
        __syncthreads();
        if (tid < BM) {
            float2 a = lse_s[tid*WARPS_N];
            #pragma unroll
            for (int w = 1; w < WARPS_N; w++) {
                float2 b = lse_s[tid*WARPS_N + w];
                float M = fmaxf(a.x, b.x);
                a = make_float2(M, a.y*__expf(a.x - M) + b.y*__expf(b.x - M));
            }
            lsepart[(size_t)(row0 + tid) * gridDim.x + blockIdx.x] = a;
        }
        return;
    }

    #pragma unroll
    for (int mt = 0; mt < MT; mt++) {
        #pragma unroll
        for (int nt = 0; nt < NT; nt++) {
            int r = row0 + wm*WM + mt*16 + gid;
            int c = col0 + wn*WN + nt*8 + (lane & 3)*2;
            float2 v0 = make_float2(acc[mt][nt][0], acc[mt][nt][1]);
            float2 v1 = make_float2(acc[mt][nt][2], acc[mt][nt][3]);
            if (bias) {
                float2 bb = *(const float2*)(bias + c);
                v0.x += bb.x; v0.y += bb.y;
                v1.x += bb.x; v1.y += bb.y;
            }
            float* p0 = C + (size_t)r * ldc + c;
            float* p1 = C + (size_t)(r+8) * ldc + c;
            if (accumulate) {
                float2 c0 = *(const float2*)p0;
                float2 c1 = *(const float2*)p1;
                v0.x += c0.x; v0.y += c0.y;
                v1.x += c1.x; v1.y += c1.y;
            }
            if (relu) {
                v0.x = fmaxf(v0.x, 0.f); v0.y = fmaxf(v0.y, 0.f);
                v1.x = fmaxf(v1.x, 0.f); v1.y = fmaxf(v1.y, 0.f);
            }
            if (roundout) {
                v0.x = tf32r(v0.x); v0.y = tf32r(v0.y);
                v1.x = tf32r(v1.x); v1.y = tf32r(v1.y);
            }
            *(float2*)p0 = v0;
            *(float2*)p1 = v1;
        }
    }
}

// ---------------- causal softmax with analytic masked mass ----------------
// Row t: real entries s<=t get exp(v*scale - m)/denom; masked entries are all 0
// pre-softmax, contributing count*exp(-m) to denom; their uniform weight
// exp(-m)/denom is emitted to wm[] for the suffix-V correction.
// Writes only columns [0, ceil((t+1)/128)*128) — AV GEMM uses K_eff=row0+128.
__global__ void softmax_kernel(float* __restrict__ S, float* __restrict__ wm)
{
    int warp = threadIdx.x >> 5;
    int lane = threadIdx.x & 31;
    size_t row = (size_t)blockIdx.x * 8 + warp;
    int t = (int)(row % T_);
    int nch = (t >> 7) + 1;
    float4* p4 = (float4*)(S + row * T_);

    float4 v[8];
    float mreal = -1e30f;
    #pragma unroll
    for (int i = 0; i < 8; i++) {
        if (i < nch) {
            int idx = i*32 + lane;
            int c   = idx * 4;
            float4 a = p4[idx];
            a.x = (c+0 <= t) ? a.x * SCALE_ : -1e30f;
            a.y = (c+1 <= t) ? a.y * SCALE_ : -1e30f;
            a.z = (c+2 <= t) ? a.z * SCALE_ : -1e30f;
            a.w = (c+3 <= t) ? a.w * SCALE_ : -1e30f;
            v[i] = a;
            mreal = fmaxf(mreal, fmaxf(fmaxf(a.x, a.y), fmaxf(a.z, a.w)));
        }
    }
    #pragma unroll
    for (int off = 16; off > 0; off >>= 1)
        mreal = fmaxf(mreal, __shfl_xor_sync(0xffffffffu, mreal, off));

    int count = T_ - 1 - t;
    float m = (count > 0) ? fmaxf(mreal, 0.f) : mreal;

    float sum = 0.f;
    #pragma unroll
    for (int i = 0; i < 8; i++) {
        if (i < nch) {
            v[i].x = __expf(v[i].x - m);
            v[i].y = __expf(v[i].y - m);
            v[i].z = __expf(v[i].z - m);
            v[i].w = __expf(v[i].w - m);
            sum += v[i].x + v[i].y + v[i].z + v[i].w;
        }
    }
    #pragma unroll
    for (int off = 16; off > 0; off >>= 1)
        sum += __shfl_xor_sync(0xffffffffu, sum, off);

    float wmask = __expf(-m);
    float inv = 1.0f / (sum + (float)count * wmask);
    #pragma unroll
    for (int i = 0; i < 8; i++) {
        if (i < nch) {
            v[i].x = tf32r(v[i].x * inv);
            v[i].y = tf32r(v[i].y * inv);
            v[i].z = tf32r(v[i].z * inv);
            v[i].w = tf32r(v[i].w * inv);
            p4[i*32 + lane] = v[i];
        }
    }
    if (lane == 0) wm[row] = wmask * inv;
}

// ---------------- V suffix sums: suf[bh][t][e] = sum_{s>t} V[b,s,h,e] ----------------
__global__ void suffixv_kernel(const float* __restrict__ qkv, float* __restrict__ suf)
{
    int bh = blockIdx.x;
    int b = bh / H_, h = bh - b * H_;
    int e = threadIdx.x;   // 64
    const float* vp = qkv + (size_t)b*T_*QKVW_ + 2*H_*HS_ + h*HS_ + e;
    float* sp = suf + (size_t)bh*T_*HS_ + e;
    float acc = 0.f;
    for (int t = T_ - 1; t >= 0; t--) {
        sp[(size_t)t*HS_] = acc;
        acc += vp[(size_t)t*QKVW_];
    }
}

// ---------------- av += wm * SufV, then tf32 round ----------------
__global__ void avcorr_kernel(const float* __restrict__ suf,
                              const float* __restrict__ wm,
                              float* __restrict__ av)
{
    int idx = blockIdx.x * blockDim.x + threadIdx.x;
    if (idx >= BT_*D_/4) return;
    int bt  = idx / (D_/4);
    int rem = idx - bt * (D_/4);
    int h   = rem / (HS_/4);
    int e4  = rem - h * (HS_/4);
    int b = bt / T_, t = bt - b * T_;
    int bh = b*H_ + h;
    float w = wm[(size_t)bh*T_ + t];
    float4 s4 = *(const float4*)&suf[((size_t)bh*T_ + t)*HS_ + e4*4];
    float4 a  = *(float4*)&av[(size_t)bt*D_ + h*HS_ + e4*4];
    a.x = tf32r(fmaf(w, s4.x, a.x));
    a.y = tf32r(fmaf(w, s4.y, a.y));
    a.z = tf32r(fmaf(w, s4.z, a.z));
    a.w = tf32r(fmaf(w, s4.w, a.w));
    *(float4*)&av[(size_t)bt*D_ + h*HS_ + e4*4] = a;
}

// ---------------- loss from LM-head partials ----------------
__global__ void lossrow2_kernel(const float2* __restrict__ part,
                                const float* __restrict__ logits,
                                const int* __restrict__ tgt,
                                float* __restrict__ rowloss)
{
    int row  = blockIdx.x;
    int lane = threadIdx.x;   // 32
    float m = -1e30f, s = 0.f;
    for (int i = lane; i < NCH_; i += 32) {
        float2 p = part[(size_t)row*NCH_ + i];
        float M = fmaxf(m, p.x);
        s = s*__expf(m - M) + p.y*__expf(p.x - M);
        m = M;
    }
    #pragma unroll
    for (int off = 16; off > 0; off >>= 1) {
        float mo = __shfl_xor_sync(0xffffffffu, m, off);
        float so = __shfl_xor_sync(0xffffffffu, s, off);
        float M = fmaxf(m, mo);
        s = s*__expf(m - M) + so*__expf(mo - M);
        m = M;
    }
    if (lane == 0)
        rowloss[row] = m + logf(s) - logits[(size_t)row*V_ + tgt[row]];
}

__global__ void lossreduce_kernel(const float* __restrict__ rowloss,
                                  float* __restrict__ out)
{
    __shared__ float red[256];
    int tid = threadIdx.x;
    float s = 0.f;
    for (int i = tid; i < BT_; i += 256) s += rowloss[i];
    red[tid] = s; __syncthreads();
    for (int off = 128; off > 0; off >>= 1) {
        if (tid < off) red[tid] += red[tid+off];
        __syncthreads();
    }
    if (tid == 0) out[0] = red[0] / (float)BT_;
}

// ---------------- host ----------------
static float* sym(const void* s)
{
    void* p = nullptr;
    cudaGetSymbolAddress(&p, s);
    return (float*)p;
}

struct GemmArgs {
    const float *A, *B; float* C; const float* bias;
    int M, N, K, lda, ldb, ldc;
    bool acc, relu, round;
    int causal;           // 0 none, 1 scores-skip, 2 causal-K
    float2* lsepart;
    int Z, zdiv;
    long long sAd, sAm, sBd, sBm, sCd, sCm;
};

static void gemm128x128(const GemmArgs& g)
{
    dim3 grid(g.N / 128, g.M / 128, g.Z);
    ntgemm_kernel<128,128,64,32><<<grid, 256>>>(
        g.A, g.B, g.C, g.bias, g.K, g.lda, g.ldb, g.ldc,
        g.acc, g.relu, g.round, g.causal, g.lsepart, g.zdiv,
        g.sAd, g.sAm, g.sBd, g.sBm, g.sCd, g.sCm);
}

static void gemm128x64(const GemmArgs& g)
{
    dim3 grid(g.N / 64, g.M / 128, g.Z);
    ntgemm_kernel<128,64,32,32><<<grid, 256>>>(
        g.A, g.B, g.C, g.bias, g.K, g.lda, g.ldb, g.ldc,
        g.acc, g.relu, g.round, g.causal, g.lsepart, g.zdiv,
        g.sAd, g.sAm, g.sBd, g.sBm, g.sCd, g.sCm);
}

static void transpose(const float* in, float* out, int R, int C,
                      int ldi, int ldo, int Z, int zdiv, int roundout,
                      long long sId, long long sIm,
                      long long sOd, long long sOm)
{
    dim3 grid(C / 32, R / 32, Z);
    transpose_kernel<<<grid, dim3(32, 8)>>>(in, out, ldi, ldo, zdiv, roundout,
                                            sId, sIm, sOd, sOm);
}

extern "C" void kernel_launch(void* const* d_in, const int* in_sizes, int n_in,
                              void* d_out, int out_size)
{
    const int*   token_ids = (const int*)d_in[0];
    const int*   targets   = (const int*)d_in[1];
    const float* tok_table = (const float*)d_in[2];
    const float* pos_table = (const float*)d_in[3];
    const float* ln1_g = (const float*)d_in[4];
    const float* ln1_b = (const float*)d_in[5];
    const float* Wq = (const float*)d_in[6];
    const float* Wk = (const float*)d_in[7];
    const float* Wv = (const float*)d_in[8];
    const float* Wo = (const float*)d_in[9];
    const float* ln2_g = (const float*)d_in[10];
    const float* ln2_b = (const float*)d_in[11];
    const float* W1 = (const float*)d_in[12];
    const float* b1 = (const float*)d_in[13];
    const float* W2 = (const float*)d_in[14];
    const float* b2 = (const float*)d_in[15];
    const float* lnf_g = (const float*)d_in[16];
    const float* lnf_b = (const float*)d_in[17];
    const float* Wlm = (const float*)d_in[18];
    const float* blm = (const float*)d_in[19];

    float* x    = sym(g_x);
    float* h    = sym(g_h);
    float* qkv  = sym(g_qkv);
    float* wp   = sym(g_wpack);
    float* woT  = sym(g_woT);
    float* w1T  = sym(g_w1T);
    float* w2T  = sym(g_w2T);
    float* wlmT = sym(g_wlmT);
    float* vT   = sym(g_vT);
    float* s    = sym(g_s);
    float* av   = sym(g_av);
    float* ffn  = sym(g_ffn);
    float* wm   = sym(g_wm);
    float* sufv = sym(g_sufv);
    float2* lsp = (float2*)sym(g_lsepart);
    float* rl   = sym(g_rowloss);

    const long long NLOGITS = (long long)BT_ * V_;
    float* out = (float*)d_out;
    bool out_has_logits = ((long long)out_size >= NLOGITS);
    float* logits = out_has_logits ? out : sym(g_logits);

    // ---- embed ----
    embed_kernel<<<(BT_*D_ + 255)/256, 256>>>(token_ids, tok_table, pos_table, x);

    // ---- weight packs ----
    for (int grp = 0; grp < 3; grp++) {
        const float* W = (grp == 0) ? Wq : (grp == 1) ? Wk : Wv;
        transpose(W, wp + (long long)grp*H_*HS_*D_, D_, HS_, HS_, D_,
                  L_*H_, H_, 1,
                  (long long)H_*D_*HS_, (long long)D_*HS_,
                  (long long)QKVW_*D_, (long long)HS_*D_);
    }
    transpose(Wo, woT, H_*HS_, D_, D_, H_*HS_, L_, 1, 1,
              (long long)H_*HS_*D_, 0, (long long)D_*H_*HS_, 0);
    transpose(W1, w1T, D_, DFF_, DFF_, D_, L_, 1, 1,
              (long long)D_*DFF_, 0, (long long)DFF_*D_, 0);
    transpose(W2, w2T, DFF_, D_, D_, DFF_, L_, 1, 1,
              (long long)DFF_*D_, 0, (long long)D_*DFF_, 0);
    transpose(Wlm, wlmT, D_, V_, V_, D_, 1, 1, 1, 0, 0, 0, 0);

    for (int l = 0; l < L_; l++) {
        ln_kernel<<<BT_, 128>>>(x, ln1_g + l*D_, ln1_b + l*D_, h);

        // fused QKV (rounded)
        {
            GemmArgs g{h, wp + (long long)l*QKVW_*D_, qkv, nullptr,
                       BT_, QKVW_, D_, D_, D_, QKVW_,
                       false, false, true, 0, nullptr, 1, 1, 0,0,0,0,0,0};
            gemm128x128(g);
        }

        // V^T for AV GEMM; V suffix sums for masked-mass correction
        transpose(qkv + 2*H_*HS_, vT, BT_, D_, QKVW_, BT_, 1, 1, 0, 0, 0, 0, 0);
        suffixv_kernel<<<B_*H_, HS_>>>(qkv, sufv);

        // scores = q @ k^T, skipping above-diagonal blocks
        {
            GemmArgs g{qkv, qkv + H_*HS_, s, nullptr,
                       T_, T_, HS_, QKVW_, QKVW_, T_,
                       false, false, false, 1, nullptr, B_*H_, H_,
                       (long long)T_*QKVW_, HS_,
                       (long long)T_*QKVW_, HS_,
                       (long long)H_*T_*T_, (long long)T_*T_};
            gemm128x128(g);
        }

        softmax_kernel<<<B_*H_*T_/8, 256>>>(s, wm);

        // av = attn @ v with causal K (masked mass corrected after)
        {
            GemmArgs g{s, vT, av, nullptr,
                       T_, HS_, T_, T_, BT_, D_,
                       false, false, false, 2, nullptr, B_*H_, H_,
                       (long long)H_*T_*T_, (long long)T_*T_,
                       (long long)T_, (long long)HS_*BT_,
                       (long long)T_*D_, HS_};
            gemm128x64(g);
        }
        avcorr_kernel<<<(BT_*D_/4 + 255)/256, 256>>>(sufv, wm, av);

        // x += av @ Wo[l]
        {
            GemmArgs g{av, woT + (long long)l*D_*H_*HS_, x, nullptr,
                       BT_, D_, H_*HS_, H_*HS_, H_*HS_, D_,
                       true, false, false, 0, nullptr, 1, 1, 0,0,0,0,0,0};
            gemm128x128(g);
        }

        ln_kernel<<<BT_, 128>>>(x, ln2_g + l*D_, ln2_b + l*D_, h);

        // ffn
        {
            GemmArgs g{h, w1T + (long long)l*DFF_*D_, ffn, b1 + l*DFF_,
                       BT_, DFF_, D_, D_, D_, DFF_,
                       false, true, true, 0, nullptr, 1, 1, 0,0,0,0,0,0};
            gemm128x128(g);
        }
        {
            GemmArgs g{ffn, w2T + (long long)l*D_*DFF_, x, b2 + l*D_,
                       BT_, D_, DFF_, DFF_, DFF_, D_,
                       true, false, false, 0, nullptr, 1, 1, 0,0,0,0,0,0};
            gemm128x128(g);
        }
    }

    ln_kernel<<<BT_, 128>>>(x, lnf_g, lnf_b, h);

    // LM head with fused per-chunk LSE partials
    {
        GemmArgs g{h, wlmT, logits, blm,
                   BT_, V_, D_, D_, D_, V_,
                   false, false, false, 0, lsp, 1, 1, 0,0,0,0,0,0};
        gemm128x128(g);
    }

    lossrow2_kernel<<<BT_, 32>>>(lsp, logits, targets, rl);
    if (out_has_logits && (long long)out_size > NLOGITS) {
        lossreduce_kernel<<<1, 256>>>(rl, out + NLOGITS);
    } else if (!out_has_logits && out_size >= 1) {
        lossreduce_kernel<<<1, 256>>>(rl, out);
    }
}